// round 11
// baseline (speedup 1.0000x reference)
#include <cuda_runtime.h>
#include <cuda_fp16.h>
#include <cstdint>

#define T_STEPS 1000
#define BATCH   512
#define NIN     128
#define HPAD    256
#define KCAT2   512                   // 2 fp16 splits x 256
#define LANES   (BATCH * HPAD)        // 131072
#define MROWS   (T_STEPS * BATCH)     // 512000
#define OUTB    (T_STEPS * BATCH * 2) // 1024000

// ---- scratch (static device memory; no allocations allowed) ----
__device__ float g_buf1[(size_t)MROWS * HPAD];   // cur1 (fp32, bias included)
__device__ __half g_s1h[(size_t)MROWS * HPAD];   // s1 spikes fp16
__device__ float g_buf2[(size_t)MROWS * HPAD];   // cur2 raw fp32
__device__ float g_cur3[(size_t)MROWS * 2];
__device__ float g_W1p[NIN * HPAD];
__device__ float g_b1p[HPAD];
__device__ float g_b2p[HPAD];
__device__ __half g_W2h[HPAD * KCAT2];  // [n=256][k'=512], 2-split fp16 per katom

// ================= helpers =================
__device__ __forceinline__ uint32_t smem_u32(const void* p) {
    return (uint32_t)__cvta_generic_to_shared(p);
}
__device__ __forceinline__ void cpasync16(uint32_t dst, const void* src) {
    asm volatile("cp.async.cg.shared.global [%0], [%1], 16;" :: "r"(dst), "l"(src));
}
__device__ __forceinline__ uint32_t swz(uint32_t off) { return off ^ ((off >> 3) & 0x70); }
__device__ __forceinline__ void ldsm4(uint32_t* r, uint32_t addr) {
    asm volatile("ldmatrix.sync.aligned.m8n8.x4.shared.b16 {%0,%1,%2,%3}, [%4];"
                 : "=r"(r[0]), "=r"(r[1]), "=r"(r[2]), "=r"(r[3]) : "r"(addr));
}
__device__ __forceinline__ void mma_f16(float* d, const uint32_t* a, const uint32_t* b) {
    asm volatile(
        "mma.sync.aligned.m16n8k16.row.col.f32.f16.f16.f32 "
        "{%0,%1,%2,%3}, {%4,%5,%6,%7}, {%8,%9}, {%0,%1,%2,%3};"
        : "+f"(d[0]), "+f"(d[1]), "+f"(d[2]), "+f"(d[3])
        : "r"(a[0]), "r"(a[1]), "r"(a[2]), "r"(a[3]), "r"(b[0]), "r"(b[1]));
}

// ================= prep kernels =================
__global__ void prep_kernel(const float* __restrict__ W1, const float* __restrict__ b1,
                            const float* __restrict__ b2) {
    int i = blockIdx.x * blockDim.x + threadIdx.x;  // 0..32767
    int k = i >> 8, n = i & 255;
    if (i < NIN * HPAD)
        g_W1p[i] = (n < 250) ? W1[k * 250 + n] : 0.0f;
    if (i < HPAD) {
        g_b1p[i] = (i < 250) ? b1[i] : 0.0f;
        g_b2p[i] = (i < 250) ? b2[i] : 0.0f;
    }
}
// W2h[n][c*64+kk] = split_{c%2}(W2[(c/2)*64+kk][n]); 2-term fp16 split
__global__ void prep_w2h_kernel(const float* __restrict__ W2) {
    int id = blockIdx.x * blockDim.x + threadIdx.x;  // 0..131071
    int n = id / KCAT2, kp = id % KCAT2;
    int c = kp >> 6, kk = kp & 63;
    int katom = c >> 1, split = c & 1;
    int k = katom * 64 + kk;
    float w = (k < 250 && n < 250) ? W2[k * 250 + n] : 0.0f;
    __half hi = __float2half_rn(w);
    float r1 = w - __half2float(hi);
    __half lo = __float2half_rn(r1);
    g_W2h[id] = (split == 0) ? hi : lo;
}

// ================= packed f32x2 helpers for layer-1 SGEMM =================
__device__ __forceinline__ void ffma2(unsigned long long& d, unsigned long long a,
                                      unsigned long long b) {
    asm("fma.rn.f32x2 %0, %1, %2, %0;" : "+l"(d) : "l"(a), "l"(b));
}
__device__ __forceinline__ unsigned long long dup2(float v) {
    unsigned long long r;
    unsigned int u = __float_as_uint(v);
    asm("mov.b64 %0, {%1, %1};" : "=l"(r) : "r"(u));
    return r;
}
__device__ __forceinline__ float2 unpack2(unsigned long long v) {
    float2 f;
    asm("mov.b64 {%0, %1}, %2;" : "=f"(f.x), "=f"(f.y) : "l"(v));
    return f;
}

// ---- layer-1 fp32 SGEMM (FFMA2), C[M,256] = A[M,128] @ W[128,256] + bias ----
#define BM 128
#define BN 128
#define BK 16
__global__ __launch_bounds__(256, 2)
void sgemm_kernel(const float* __restrict__ A, const float* __restrict__ W,
                  const float* __restrict__ bias, float* __restrict__ C, int K) {
    __shared__ __align__(16) float As[BK][BM];
    __shared__ __align__(16) float Ws[BK][BN];
    const int tid = threadIdx.x;
    const size_t m0 = (size_t)blockIdx.x * BM;
    const int n0 = blockIdx.y * BN;
    const int tr = tid >> 4, tc = tid & 15;
    const int aRow = tid >> 1, aCol = (tid & 1) * 8;
    const int wRow = tid >> 4, wCol = (tid & 15) * 8;

    unsigned long long acc[8][4];
#pragma unroll
    for (int i = 0; i < 8; i++)
#pragma unroll
        for (int jj = 0; jj < 4; jj++) acc[i][jj] = 0ULL;

    const float* Abase = A + (m0 + aRow) * (size_t)K;
    const float* Wbase = W + (size_t)wRow * HPAD + n0 + wCol;

    for (int k0 = 0; k0 < K; k0 += BK) {
        float4 av0 = *(const float4*)(Abase + k0 + aCol);
        float4 av1 = *(const float4*)(Abase + k0 + aCol + 4);
        As[aCol + 0][aRow] = av0.x; As[aCol + 1][aRow] = av0.y;
        As[aCol + 2][aRow] = av0.z; As[aCol + 3][aRow] = av0.w;
        As[aCol + 4][aRow] = av1.x; As[aCol + 5][aRow] = av1.y;
        As[aCol + 6][aRow] = av1.z; As[aCol + 7][aRow] = av1.w;
        float4 wv0 = *(const float4*)(Wbase + (size_t)k0 * HPAD);
        float4 wv1 = *(const float4*)(Wbase + (size_t)k0 * HPAD + 4);
        *(float4*)(&Ws[wRow][wCol]) = wv0;
        *(float4*)(&Ws[wRow][wCol + 4]) = wv1;
        __syncthreads();
#pragma unroll
        for (int k = 0; k < BK; k++) {
            float ra[8];
            *(float4*)(&ra[0]) = *(const float4*)(&As[k][tr * 8]);
            *(float4*)(&ra[4]) = *(const float4*)(&As[k][tr * 8 + 4]);
            unsigned long long rb[4];
            rb[0] = *(const unsigned long long*)(&Ws[k][tc * 4]);
            rb[1] = *(const unsigned long long*)(&Ws[k][tc * 4 + 2]);
            rb[2] = *(const unsigned long long*)(&Ws[k][64 + tc * 4]);
            rb[3] = *(const unsigned long long*)(&Ws[k][64 + tc * 4 + 2]);
#pragma unroll
            for (int i = 0; i < 8; i++) {
                unsigned long long aa = dup2(ra[i]);
                ffma2(acc[i][0], aa, rb[0]);
                ffma2(acc[i][1], aa, rb[1]);
                ffma2(acc[i][2], aa, rb[2]);
                ffma2(acc[i][3], aa, rb[3]);
            }
        }
        __syncthreads();
    }
    const int nA = n0 + tc * 4, nB = n0 + 64 + tc * 4;
    float4 bvA = *(const float4*)(bias + nA);
    float4 bvB = *(const float4*)(bias + nB);
#pragma unroll
    for (int i = 0; i < 8; i++) {
        size_t rowOff = (m0 + tr * 8 + i) * (size_t)HPAD;
        float2 p0 = unpack2(acc[i][0]), p1 = unpack2(acc[i][1]);
        float2 p2 = unpack2(acc[i][2]), p3 = unpack2(acc[i][3]);
        float4 cA = {p0.x + bvA.x, p0.y + bvA.y, p1.x + bvA.z, p1.y + bvA.w};
        float4 cB = {p2.x + bvB.x, p2.y + bvB.y, p3.x + bvB.z, p3.y + bvB.w};
        *(float4*)(C + rowOff + nA) = cA;
        *(float4*)(C + rowOff + nB) = cB;
    }
}

// ================= layer-2 GEMM via mma.sync fp16 (2-split, K=512) =================
#define OFF_A0 0
#define OFF_A1 16384
#define OFF_B0 32768
#define OFF_B1 49152
#define G2_SMEM 65536
#define NCHUNK 8

__global__ __launch_bounds__(256, 2)
void gemm2_mma_kernel(const __half* __restrict__ s1h,
                      const __half* __restrict__ W2h,
                      float* __restrict__ out) {
    extern __shared__ __align__(1024) char smem[];
    const uint32_t sb = smem_u32(smem);
    const int tid = threadIdx.x;
    const int warp = tid >> 5, lane = tid & 31;
    const int g = lane >> 2, tig = lane & 3;
    const int wm = warp >> 2, wn = warp & 3;
    const size_t m0 = (size_t)blockIdx.x * 128;
    const int n0 = blockIdx.y * 128;

    const int ldr = tid >> 1;
    const int ldh = tid & 1;

    const int arow_l = lane & 15, ahalf = lane >> 4;
    const uint32_t a_off0 = (uint32_t)((wm * 64 + arow_l) * 128 + ahalf * 16);
    const int lane8 = lane & 7, laneg = lane >> 3;
    const uint32_t b_off0 =
        (uint32_t)((wn * 32 + ((laneg & 2) ? 8 : 0) + lane8) * 128 + (laneg & 1) * 16);

    float acc[4][4][4];
#pragma unroll
    for (int mf = 0; mf < 4; mf++)
#pragma unroll
        for (int nf = 0; nf < 4; nf++)
#pragma unroll
            for (int q = 0; q < 4; q++) acc[mf][nf][q] = 0.0f;

    const __half* asrc = s1h + (m0 + ldr) * HPAD + ldh * 32;
    const __half* bsrc = W2h + (size_t)(n0 + ldr) * KCAT2 + ldh * 32;
    const uint32_t ldst = swz((uint32_t)(ldr * 128 + ldh * 64));

#pragma unroll
    for (int j = 0; j < 4; j++) cpasync16(sb + OFF_A0 + (ldst ^ (j * 16)), asrc + j * 8);
#pragma unroll
    for (int j = 0; j < 4; j++) cpasync16(sb + OFF_B0 + (ldst ^ (j * 16)), bsrc + j * 8);
    asm volatile("cp.async.commit_group;" ::: "memory");

#pragma unroll 1
    for (int c = 0; c < NCHUNK; c++) {
        if (c < NCHUNK - 1) {
            const int cn = c + 1;
            if ((cn & 1) == 0) {
                const uint32_t ab = sb + (((cn >> 1) & 1) ? OFF_A1 : OFF_A0);
                const __half* src = asrc + (cn >> 1) * 64;
#pragma unroll
                for (int j = 0; j < 4; j++) cpasync16(ab + (ldst ^ (j * 16)), src + j * 8);
            }
            const uint32_t bb = sb + ((cn & 1) ? OFF_B1 : OFF_B0);
            const __half* src = bsrc + cn * 64;
#pragma unroll
            for (int j = 0; j < 4; j++) cpasync16(bb + (ldst ^ (j * 16)), src + j * 8);
            asm volatile("cp.async.commit_group;" ::: "memory");
            asm volatile("cp.async.wait_group 1;" ::: "memory");
        } else {
            asm volatile("cp.async.wait_group 0;" ::: "memory");
        }
        __syncthreads();

        const uint32_t ab = sb + (((c >> 1) & 1) ? OFF_A1 : OFF_A0);
        const uint32_t bb = sb + ((c & 1) ? OFF_B1 : OFF_B0);
#pragma unroll
        for (int ks = 0; ks < 4; ks++) {
            uint32_t afr[4][4];
#pragma unroll
            for (int mf = 0; mf < 4; mf++)
                ldsm4(afr[mf], ab + swz(a_off0 + (uint32_t)(mf * 16 * 128 + ks * 32)));
            uint32_t bfr[4][2];
            ldsm4(&bfr[0][0], bb + swz(b_off0 + (uint32_t)(ks * 32)));
            ldsm4(&bfr[2][0], bb + swz(b_off0 + (uint32_t)(16 * 128 + ks * 32)));
#pragma unroll
            for (int mf = 0; mf < 4; mf++)
#pragma unroll
                for (int nf = 0; nf < 4; nf++)
                    mma_f16(acc[mf][nf], afr[mf], bfr[nf]);
        }
        __syncthreads();
    }

#pragma unroll
    for (int mf = 0; mf < 4; mf++) {
        size_t r0 = (m0 + wm * 64 + mf * 16 + g) * HPAD;
#pragma unroll
        for (int nf = 0; nf < 4; nf++) {
            int col = n0 + wn * 32 + nf * 8 + tig * 2;
            *(float2*)(out + r0 + col) = make_float2(acc[mf][nf][0], acc[mf][nf][1]);
            *(float2*)(out + r0 + 8 * HPAD + col) = make_float2(acc[mf][nf][2], acc[mf][nf][3]);
        }
    }
}

// ================= LIF scan 1 (reads cur1 with bias, writes fp16 spikes) =================
__global__ void lif_scan1_kernel(const float* __restrict__ buf,
                                 __half* __restrict__ s1h) {
    int lane = blockIdx.x * blockDim.x + threadIdx.x;  // 0..131071
    float m = 0.0f;
    size_t idx = lane;
#pragma unroll 8
    for (int t = 0; t < T_STEPS; t++) {
        float cur = buf[idx];
        float r = (m > 1.0f) ? 1.0f : 0.0f;
        m = __fadd_rn(__fadd_rn(__fmul_rn(0.9f, m), cur), -r);
        s1h[idx] = __float2half((m > 1.0f) ? 1.0f : 0.0f);
        idx += LANES;
    }
}

// ================= fused LIF scan 2 + layer-3 GEMM =================
// block b handles batch b: 256 threads = 256 hidden lanes; s2 never hits DRAM.
__global__ __launch_bounds__(256)
void lif2_gemm3_kernel(const float* __restrict__ buf2, const float* __restrict__ b2p,
                       const float* __restrict__ W3, const float* __restrict__ b3,
                       float* __restrict__ cur3) {
    __shared__ float part[2][8][2];
    const int b = blockIdx.x, tid = threadIdx.x;
    const int warp = tid >> 5, lane = tid & 31;
    const float bv = b2p[tid];
    const float w0 = (tid < 250) ? W3[tid * 2] : 0.0f;
    const float w1 = (tid < 250) ? W3[tid * 2 + 1] : 0.0f;
    const float b30 = b3[0], b31 = b3[1];
    const size_t base = (size_t)b * HPAD + tid;

    float m = 0.0f;
    float cur = __fadd_rn(buf2[base], bv);
#pragma unroll 2
    for (int t = 0; t < T_STEPS; t++) {
        float nxt = 0.0f;
        if (t < T_STEPS - 1)
            nxt = __fadd_rn(buf2[base + (size_t)(t + 1) * LANES], bv);
        float r = (m > 1.0f) ? 1.0f : 0.0f;
        m = __fadd_rn(__fadd_rn(__fmul_rn(0.9f, m), cur), -r);
        bool s = (m > 1.0f);
        float p0 = s ? w0 : 0.0f;
        float p1 = s ? w1 : 0.0f;
#pragma unroll
        for (int off = 16; off; off >>= 1) {
            p0 += __shfl_xor_sync(0xffffffffu, p0, off);
            p1 += __shfl_xor_sync(0xffffffffu, p1, off);
        }
        if (lane == 0) { part[t & 1][warp][0] = p0; part[t & 1][warp][1] = p1; }
        __syncthreads();
        if (tid < 2) {
            float sum = part[t & 1][0][tid] + part[t & 1][1][tid] + part[t & 1][2][tid] +
                        part[t & 1][3][tid] + part[t & 1][4][tid] + part[t & 1][5][tid] +
                        part[t & 1][6][tid] + part[t & 1][7][tid];
            cur3[((size_t)t * BATCH + b) * 2 + tid] = sum + (tid ? b31 : b30);
        }
        cur = nxt;
    }
}

// ================= LIF scan 3 + output write =================
__global__ void lif3_kernel(const float* __restrict__ cur3, float* __restrict__ out) {
    int lane = blockIdx.x * blockDim.x + threadIdx.x;  // b*2+o
    float m = 0.0f;
#pragma unroll 16
    for (int t = 0; t < T_STEPS; t++) {
        float cur = cur3[t * 1024 + lane];
        float r = (m > 1.0f) ? 1.0f : 0.0f;
        m = __fadd_rn(__fadd_rn(__fmul_rn(0.9f, m), cur), -r);
        out[t * 1024 + lane] = (m > 1.0f) ? 1.0f : 0.0f;
        out[OUTB + t * 1024 + lane] = m;
    }
}

extern "C" void kernel_launch(void* const* d_in, const int* in_sizes, int n_in,
                              void* d_out, int out_size) {
    const float* x  = (const float*)d_in[0];
    const float* W1 = (const float*)d_in[1];
    const float* b1 = (const float*)d_in[2];
    const float* W2 = (const float*)d_in[3];
    const float* b2 = (const float*)d_in[4];
    const float* W3 = (const float*)d_in[5];
    const float* b3 = (const float*)d_in[6];
    float* out = (float*)d_out;

    float *buf1, *buf2, *cur3, *W1p, *b1p, *b2p;
    __half *s1h, *W2h;
    cudaGetSymbolAddress((void**)&buf1, g_buf1);
    cudaGetSymbolAddress((void**)&buf2, g_buf2);
    cudaGetSymbolAddress((void**)&cur3, g_cur3);
    cudaGetSymbolAddress((void**)&W1p, g_W1p);
    cudaGetSymbolAddress((void**)&b1p, g_b1p);
    cudaGetSymbolAddress((void**)&b2p, g_b2p);
    cudaGetSymbolAddress((void**)&s1h, g_s1h);
    cudaGetSymbolAddress((void**)&W2h, g_W2h);

    cudaFuncSetAttribute(gemm2_mma_kernel,
                         cudaFuncAttributeMaxDynamicSharedMemorySize, G2_SMEM);

    prep_kernel<<<128, 256>>>(W1, b1, b2);
    prep_w2h_kernel<<<512, 256>>>(W2);

    // layer 1: cur1 = x @ W1 + b1 (exact FFMA2 fp32)
    sgemm_kernel<<<dim3(MROWS / BM, HPAD / BN), 256>>>(x, W1p, b1p, buf1, NIN);
    lif_scan1_kernel<<<LANES / 256, 256>>>(buf1, s1h);

    // layer 2: cur2 = s1 @ (W2hi + W2lo) via fp16 mma.sync (K=512), raw output
    gemm2_mma_kernel<<<dim3(MROWS / 128, 2), 256, G2_SMEM>>>(s1h, W2h, buf2);

    // fused: LIF-2 scan + layer-3 GEMM (s2 stays in registers)
    lif2_gemm3_kernel<<<BATCH, 256>>>(buf2, b2p, W3, b3, cur3);

    // layer-3 scan + outputs
    lif3_kernel<<<4, 256>>>(cur3, out);
}

// round 13
// speedup vs baseline: 1.0115x; 1.0115x over previous
#include <cuda_runtime.h>
#include <cuda_fp16.h>
#include <cstdint>

#define T_STEPS 1000
#define BATCH   512
#define NIN     128
#define HPAD    256
#define KCAT2   512                   // 2 fp16 splits x 256
#define LANES   (BATCH * HPAD)        // 131072
#define MROWS   (T_STEPS * BATCH)     // 512000
#define OUTB    (T_STEPS * BATCH * 2) // 1024000

// ---- scratch (static device memory; no allocations allowed) ----
__device__ float g_buf1[(size_t)MROWS * HPAD];   // cur1 (fp32, bias included)
__device__ __half g_s1h[(size_t)MROWS * HPAD];   // s1 spikes fp16
__device__ float g_buf2[(size_t)MROWS * HPAD];   // cur2 raw fp32
__device__ __half g_s2h[(size_t)MROWS * HPAD];   // s2 spikes fp16
__device__ float g_cur3[(size_t)MROWS * 2];
__device__ float g_W1p[NIN * HPAD];
__device__ float g_b1p[HPAD];
__device__ float g_b2p[HPAD];
__device__ __half g_W2h[HPAD * KCAT2];  // [n=256][k'=512], 2-split fp16 per katom

// ================= helpers =================
__device__ __forceinline__ uint32_t smem_u32(const void* p) {
    return (uint32_t)__cvta_generic_to_shared(p);
}
__device__ __forceinline__ void cpasync16(uint32_t dst, const void* src) {
    asm volatile("cp.async.cg.shared.global [%0], [%1], 16;" :: "r"(dst), "l"(src));
}
__device__ __forceinline__ uint32_t swz(uint32_t off) { return off ^ ((off >> 3) & 0x70); }
__device__ __forceinline__ void ldsm4(uint32_t* r, uint32_t addr) {
    asm volatile("ldmatrix.sync.aligned.m8n8.x4.shared.b16 {%0,%1,%2,%3}, [%4];"
                 : "=r"(r[0]), "=r"(r[1]), "=r"(r[2]), "=r"(r[3]) : "r"(addr));
}
__device__ __forceinline__ void mma_f16(float* d, const uint32_t* a, const uint32_t* b) {
    asm volatile(
        "mma.sync.aligned.m16n8k16.row.col.f32.f16.f16.f32 "
        "{%0,%1,%2,%3}, {%4,%5,%6,%7}, {%8,%9}, {%0,%1,%2,%3};"
        : "+f"(d[0]), "+f"(d[1]), "+f"(d[2]), "+f"(d[3])
        : "r"(a[0]), "r"(a[1]), "r"(a[2]), "r"(a[3]), "r"(b[0]), "r"(b[1]));
}

// ================= prep kernels =================
__global__ void prep_kernel(const float* __restrict__ W1, const float* __restrict__ b1,
                            const float* __restrict__ b2) {
    int i = blockIdx.x * blockDim.x + threadIdx.x;  // 0..32767
    int k = i >> 8, n = i & 255;
    if (i < NIN * HPAD)
        g_W1p[i] = (n < 250) ? W1[k * 250 + n] : 0.0f;
    if (i < HPAD) {
        g_b1p[i] = (i < 250) ? b1[i] : 0.0f;
        g_b2p[i] = (i < 250) ? b2[i] : 0.0f;
    }
}
// W2h[n][c*64+kk] = split_{c%2}(W2[(c/2)*64+kk][n]); 2-term fp16 split
__global__ void prep_w2h_kernel(const float* __restrict__ W2) {
    int id = blockIdx.x * blockDim.x + threadIdx.x;  // 0..131071
    int n = id / KCAT2, kp = id % KCAT2;
    int c = kp >> 6, kk = kp & 63;
    int katom = c >> 1, split = c & 1;
    int k = katom * 64 + kk;
    float w = (k < 250 && n < 250) ? W2[k * 250 + n] : 0.0f;
    __half hi = __float2half_rn(w);
    float r1 = w - __half2float(hi);
    __half lo = __float2half_rn(r1);
    g_W2h[id] = (split == 0) ? hi : lo;
}

// ================= packed f32x2 helpers for layer-1 SGEMM =================
__device__ __forceinline__ void ffma2(unsigned long long& d, unsigned long long a,
                                      unsigned long long b) {
    asm("fma.rn.f32x2 %0, %1, %2, %0;" : "+l"(d) : "l"(a), "l"(b));
}
__device__ __forceinline__ float2 unpack2(unsigned long long v) {
    float2 f;
    asm("mov.b64 {%0, %1}, %2;" : "=f"(f.x), "=f"(f.y) : "l"(v));
    return f;
}

// ---- layer-1 fp32 SGEMM (FFMA2, A pre-duplicated in smem) ----
// C[M,256] = A[M,128] @ W[128,256] + bias
#define BM 128
#define BN 128
#define BK 16
__global__ __launch_bounds__(256, 2)
void sgemm_kernel(const float* __restrict__ A, const float* __restrict__ W,
                  const float* __restrict__ bias, float* __restrict__ C, int K) {
    __shared__ __align__(16) float As[BK][2 * BM];   // duplicated pairs: [2m]=[2m+1]=a_m
    __shared__ __align__(16) float Ws[BK][BN];
    const int tid = threadIdx.x;
    const size_t m0 = (size_t)blockIdx.x * BM;
    const int n0 = blockIdx.y * BN;
    const int tr = tid >> 4, tc = tid & 15;
    const int aRow = tid >> 1, aCol = (tid & 1) * 8;
    const int wRow = tid >> 4, wCol = (tid & 15) * 8;

    unsigned long long acc[8][4];
#pragma unroll
    for (int i = 0; i < 8; i++)
#pragma unroll
        for (int jj = 0; jj < 4; jj++) acc[i][jj] = 0ULL;

    const float* Abase = A + (m0 + aRow) * (size_t)K;
    const float* Wbase = W + (size_t)wRow * HPAD + n0 + wCol;

    for (int k0 = 0; k0 < K; k0 += BK) {
        float4 av0 = *(const float4*)(Abase + k0 + aCol);
        float4 av1 = *(const float4*)(Abase + k0 + aCol + 4);
        // duplicated stores: As[k][2r] = As[k][2r+1] = a
        *(float2*)(&As[aCol + 0][2 * aRow]) = make_float2(av0.x, av0.x);
        *(float2*)(&As[aCol + 1][2 * aRow]) = make_float2(av0.y, av0.y);
        *(float2*)(&As[aCol + 2][2 * aRow]) = make_float2(av0.z, av0.z);
        *(float2*)(&As[aCol + 3][2 * aRow]) = make_float2(av0.w, av0.w);
        *(float2*)(&As[aCol + 4][2 * aRow]) = make_float2(av1.x, av1.x);
        *(float2*)(&As[aCol + 5][2 * aRow]) = make_float2(av1.y, av1.y);
        *(float2*)(&As[aCol + 6][2 * aRow]) = make_float2(av1.z, av1.z);
        *(float2*)(&As[aCol + 7][2 * aRow]) = make_float2(av1.w, av1.w);
        float4 wv0 = *(const float4*)(Wbase + (size_t)k0 * HPAD);
        float4 wv1 = *(const float4*)(Wbase + (size_t)k0 * HPAD + 4);
        *(float4*)(&Ws[wRow][wCol]) = wv0;
        *(float4*)(&Ws[wRow][wCol + 4]) = wv1;
        __syncthreads();
#pragma unroll
        for (int k = 0; k < BK; k++) {
            // 16 consecutive floats = 8 dup-pairs for rows tr*8 .. tr*8+7
            unsigned long long ad[8];
            *(ulonglong2*)(&ad[0]) = *(const ulonglong2*)(&As[k][tr * 16]);
            *(ulonglong2*)(&ad[2]) = *(const ulonglong2*)(&As[k][tr * 16 + 4]);
            *(ulonglong2*)(&ad[4]) = *(const ulonglong2*)(&As[k][tr * 16 + 8]);
            *(ulonglong2*)(&ad[6]) = *(const ulonglong2*)(&As[k][tr * 16 + 12]);
            unsigned long long rb[4];
            rb[0] = *(const unsigned long long*)(&Ws[k][tc * 4]);
            rb[1] = *(const unsigned long long*)(&Ws[k][tc * 4 + 2]);
            rb[2] = *(const unsigned long long*)(&Ws[k][64 + tc * 4]);
            rb[3] = *(const unsigned long long*)(&Ws[k][64 + tc * 4 + 2]);
#pragma unroll
            for (int i = 0; i < 8; i++) {
                ffma2(acc[i][0], ad[i], rb[0]);
                ffma2(acc[i][1], ad[i], rb[1]);
                ffma2(acc[i][2], ad[i], rb[2]);
                ffma2(acc[i][3], ad[i], rb[3]);
            }
        }
        __syncthreads();
    }
    const int nA = n0 + tc * 4, nB = n0 + 64 + tc * 4;
    float4 bvA = *(const float4*)(bias + nA);
    float4 bvB = *(const float4*)(bias + nB);
#pragma unroll
    for (int i = 0; i < 8; i++) {
        size_t rowOff = (m0 + tr * 8 + i) * (size_t)HPAD;
        float2 p0 = unpack2(acc[i][0]), p1 = unpack2(acc[i][1]);
        float2 p2 = unpack2(acc[i][2]), p3 = unpack2(acc[i][3]);
        float4 cA = {p0.x + bvA.x, p0.y + bvA.y, p1.x + bvA.z, p1.y + bvA.w};
        float4 cB = {p2.x + bvB.x, p2.y + bvB.y, p3.x + bvB.z, p3.y + bvB.w};
        *(float4*)(C + rowOff + nA) = cA;
        *(float4*)(C + rowOff + nB) = cB;
    }
}

// ================= layer-2 GEMM via mma.sync fp16 (2-split, K=512) =================
#define OFF_A0 0
#define OFF_A1 16384
#define OFF_B0 32768
#define OFF_B1 49152
#define G2_SMEM 65536
#define NCHUNK 8

__global__ __launch_bounds__(256, 2)
void gemm2_mma_kernel(const __half* __restrict__ s1h,
                      const __half* __restrict__ W2h,
                      float* __restrict__ out) {
    extern __shared__ __align__(1024) char smem[];
    const uint32_t sb = smem_u32(smem);
    const int tid = threadIdx.x;
    const int warp = tid >> 5, lane = tid & 31;
    const int g = lane >> 2, tig = lane & 3;
    const int wm = warp >> 2, wn = warp & 3;
    const size_t m0 = (size_t)blockIdx.x * 128;
    const int n0 = blockIdx.y * 128;

    const int ldr = tid >> 1;
    const int ldh = tid & 1;

    const int arow_l = lane & 15, ahalf = lane >> 4;
    const uint32_t a_off0 = (uint32_t)((wm * 64 + arow_l) * 128 + ahalf * 16);
    const int lane8 = lane & 7, laneg = lane >> 3;
    const uint32_t b_off0 =
        (uint32_t)((wn * 32 + ((laneg & 2) ? 8 : 0) + lane8) * 128 + (laneg & 1) * 16);

    float acc[4][4][4];
#pragma unroll
    for (int mf = 0; mf < 4; mf++)
#pragma unroll
        for (int nf = 0; nf < 4; nf++)
#pragma unroll
            for (int q = 0; q < 4; q++) acc[mf][nf][q] = 0.0f;

    const __half* asrc = s1h + (m0 + ldr) * HPAD + ldh * 32;
    const __half* bsrc = W2h + (size_t)(n0 + ldr) * KCAT2 + ldh * 32;
    const uint32_t ldst = swz((uint32_t)(ldr * 128 + ldh * 64));

#pragma unroll
    for (int j = 0; j < 4; j++) cpasync16(sb + OFF_A0 + (ldst ^ (j * 16)), asrc + j * 8);
#pragma unroll
    for (int j = 0; j < 4; j++) cpasync16(sb + OFF_B0 + (ldst ^ (j * 16)), bsrc + j * 8);
    asm volatile("cp.async.commit_group;" ::: "memory");

#pragma unroll 1
    for (int c = 0; c < NCHUNK; c++) {
        if (c < NCHUNK - 1) {
            const int cn = c + 1;
            if ((cn & 1) == 0) {
                const uint32_t ab = sb + (((cn >> 1) & 1) ? OFF_A1 : OFF_A0);
                const __half* src = asrc + (cn >> 1) * 64;
#pragma unroll
                for (int j = 0; j < 4; j++) cpasync16(ab + (ldst ^ (j * 16)), src + j * 8);
            }
            const uint32_t bb = sb + ((cn & 1) ? OFF_B1 : OFF_B0);
            const __half* src = bsrc + cn * 64;
#pragma unroll
            for (int j = 0; j < 4; j++) cpasync16(bb + (ldst ^ (j * 16)), src + j * 8);
            asm volatile("cp.async.commit_group;" ::: "memory");
            asm volatile("cp.async.wait_group 1;" ::: "memory");
        } else {
            asm volatile("cp.async.wait_group 0;" ::: "memory");
        }
        __syncthreads();

        const uint32_t ab = sb + (((c >> 1) & 1) ? OFF_A1 : OFF_A0);
        const uint32_t bb = sb + ((c & 1) ? OFF_B1 : OFF_B0);
#pragma unroll
        for (int ks = 0; ks < 4; ks++) {
            uint32_t afr[4][4];
#pragma unroll
            for (int mf = 0; mf < 4; mf++)
                ldsm4(afr[mf], ab + swz(a_off0 + (uint32_t)(mf * 16 * 128 + ks * 32)));
            uint32_t bfr[4][2];
            ldsm4(&bfr[0][0], bb + swz(b_off0 + (uint32_t)(ks * 32)));
            ldsm4(&bfr[2][0], bb + swz(b_off0 + (uint32_t)(16 * 128 + ks * 32)));
#pragma unroll
            for (int mf = 0; mf < 4; mf++)
#pragma unroll
                for (int nf = 0; nf < 4; nf++)
                    mma_f16(acc[mf][nf], afr[mf], bfr[nf]);
        }
        __syncthreads();
    }

#pragma unroll
    for (int mf = 0; mf < 4; mf++) {
        size_t r0 = (m0 + wm * 64 + mf * 16 + g) * HPAD;
#pragma unroll
        for (int nf = 0; nf < 4; nf++) {
            int col = n0 + wn * 32 + nf * 8 + tig * 2;
            *(float2*)(out + r0 + col) = make_float2(acc[mf][nf][0], acc[mf][nf][1]);
            *(float2*)(out + r0 + 8 * HPAD + col) = make_float2(acc[mf][nf][2], acc[mf][nf][3]);
        }
    }
}

// ================= LIF scans (1 lane per thread) =================
__global__ void lif_scan1_kernel(const float* __restrict__ buf,
                                 __half* __restrict__ s1h) {
    int lane = blockIdx.x * blockDim.x + threadIdx.x;  // 0..131071
    float m = 0.0f;
    size_t idx = lane;
#pragma unroll 8
    for (int t = 0; t < T_STEPS; t++) {
        float cur = buf[idx];
        float r = (m > 1.0f) ? 1.0f : 0.0f;
        m = __fadd_rn(__fadd_rn(__fmul_rn(0.9f, m), cur), -r);
        s1h[idx] = __float2half((m > 1.0f) ? 1.0f : 0.0f);
        idx += LANES;
    }
}
__global__ void lif_scan2_kernel(const float* __restrict__ buf,
                                 const float* __restrict__ bias,
                                 __half* __restrict__ s2h) {
    int lane = blockIdx.x * blockDim.x + threadIdx.x;
    float bv = bias[lane & 255];
    float m = 0.0f;
    size_t idx = lane;
#pragma unroll 8
    for (int t = 0; t < T_STEPS; t++) {
        float cur = __fadd_rn(buf[idx], bv);
        float r = (m > 1.0f) ? 1.0f : 0.0f;
        m = __fadd_rn(__fadd_rn(__fmul_rn(0.9f, m), cur), -r);
        s2h[idx] = __float2half((m > 1.0f) ? 1.0f : 0.0f);
        idx += LANES;
    }
}

// ---- layer 3 GEMM: warp-per-row dot over fp16 spikes, N=2, K=256 (pad cols = 0) ----
__global__ __launch_bounds__(256)
void gemm3_kernel(const __half* __restrict__ S2, const float* __restrict__ W3,
                  const float* __restrict__ b3, float* __restrict__ cur3) {
    __shared__ float w0[HPAD], w1[HPAD];
    int tid = threadIdx.x;
    if (tid < 250) { w0[tid] = W3[tid * 2]; w1[tid] = W3[tid * 2 + 1]; }
    else           { w0[tid] = 0.0f;        w1[tid] = 0.0f; }
    __syncthreads();
    int warp = tid >> 5, lane = tid & 31;
    size_t row = (size_t)blockIdx.x * 8 + warp;
    const uint4* p = (const uint4*)(S2 + row * HPAD);
    uint4 v = p[lane];
    const __half2* h = (const __half2*)&v;
    float a0 = 0.0f, a1 = 0.0f;
    int k0 = lane * 8;
#pragma unroll
    for (int j = 0; j < 4; j++) {
        float2 f = __half22float2(h[j]);
        int k = k0 + j * 2;
        a0 = fmaf(f.x, w0[k], a0); a0 = fmaf(f.y, w0[k + 1], a0);
        a1 = fmaf(f.x, w1[k], a1); a1 = fmaf(f.y, w1[k + 1], a1);
    }
#pragma unroll
    for (int off = 16; off; off >>= 1) {
        a0 += __shfl_xor_sync(0xffffffffu, a0, off);
        a1 += __shfl_xor_sync(0xffffffffu, a1, off);
    }
    if (lane == 0) {
        cur3[row * 2 + 0] = a0 + b3[0];
        cur3[row * 2 + 1] = a1 + b3[1];
    }
}

__global__ void lif3_kernel(const float* __restrict__ cur3, float* __restrict__ out) {
    int lane = blockIdx.x * blockDim.x + threadIdx.x;
    float m = 0.0f;
#pragma unroll 16
    for (int t = 0; t < T_STEPS; t++) {
        float cur = cur3[t * 1024 + lane];
        float r = (m > 1.0f) ? 1.0f : 0.0f;
        m = __fadd_rn(__fadd_rn(__fmul_rn(0.9f, m), cur), -r);
        out[t * 1024 + lane] = (m > 1.0f) ? 1.0f : 0.0f;
        out[OUTB + t * 1024 + lane] = m;
    }
}

extern "C" void kernel_launch(void* const* d_in, const int* in_sizes, int n_in,
                              void* d_out, int out_size) {
    const float* x  = (const float*)d_in[0];
    const float* W1 = (const float*)d_in[1];
    const float* b1 = (const float*)d_in[2];
    const float* W2 = (const float*)d_in[3];
    const float* b2 = (const float*)d_in[4];
    const float* W3 = (const float*)d_in[5];
    const float* b3 = (const float*)d_in[6];
    float* out = (float*)d_out;

    float *buf1, *buf2, *cur3, *W1p, *b1p, *b2p;
    __half *s1h, *s2h, *W2h;
    cudaGetSymbolAddress((void**)&buf1, g_buf1);
    cudaGetSymbolAddress((void**)&buf2, g_buf2);
    cudaGetSymbolAddress((void**)&cur3, g_cur3);
    cudaGetSymbolAddress((void**)&W1p, g_W1p);
    cudaGetSymbolAddress((void**)&b1p, g_b1p);
    cudaGetSymbolAddress((void**)&b2p, g_b2p);
    cudaGetSymbolAddress((void**)&s1h, g_s1h);
    cudaGetSymbolAddress((void**)&s2h, g_s2h);
    cudaGetSymbolAddress((void**)&W2h, g_W2h);

    cudaFuncSetAttribute(gemm2_mma_kernel,
                         cudaFuncAttributeMaxDynamicSharedMemorySize, G2_SMEM);

    prep_kernel<<<128, 256>>>(W1, b1, b2);
    prep_w2h_kernel<<<512, 256>>>(W2);

    // layer 1: cur1 = x @ W1 + b1 (exact FFMA2 fp32, A-dup smem)
    sgemm_kernel<<<dim3(MROWS / BM, HPAD / BN), 256>>>(x, W1p, b1p, buf1, NIN);
    lif_scan1_kernel<<<LANES / 256, 256>>>(buf1, s1h);

    // layer 2: cur2 = s1 @ (W2hi + W2lo) via fp16 mma.sync (K=512); bias in scan
    gemm2_mma_kernel<<<dim3(MROWS / 128, 2), 256, G2_SMEM>>>(s1h, W2h, buf2);
    lif_scan2_kernel<<<LANES / 256, 256>>>(buf2, b2p, s2h);

    // layer 3
    gemm3_kernel<<<MROWS / 8, 256>>>(s2h, W3, b3, cur3);
    lif3_kernel<<<4, 256>>>(cur3, out);
}

// round 14
// speedup vs baseline: 1.1046x; 1.0921x over previous
#include <cuda_runtime.h>
#include <cuda_fp16.h>
#include <cstdint>

#define T_STEPS 1000
#define BATCH   512
#define NIN     128
#define HPAD    256
#define KCAT2   512                   // 2 fp16 splits x 256
#define LANES   (BATCH * HPAD)        // 131072
#define MROWS   (T_STEPS * BATCH)     // 512000
#define OUTB    (T_STEPS * BATCH * 2) // 1024000

// ---- scratch (static device memory; no allocations allowed) ----
__device__ float g_buf1[(size_t)MROWS * HPAD];   // cur1 (fp32, bias included)
__device__ __half g_s1h[(size_t)MROWS * HPAD];   // s1 spikes fp16
__device__ float g_buf2[(size_t)MROWS * HPAD];   // cur2 raw fp32
__device__ __half g_s2h[(size_t)MROWS * HPAD];   // s2 spikes fp16
__device__ float g_cur3[(size_t)MROWS * 2];
__device__ float g_W1p[NIN * HPAD];
__device__ float g_b1p[HPAD];
__device__ float g_b2p[HPAD];
__device__ __half g_W2h[HPAD * KCAT2];  // [n=256][k'=512], 2-split fp16 per katom

// ================= helpers =================
__device__ __forceinline__ uint32_t smem_u32(const void* p) {
    return (uint32_t)__cvta_generic_to_shared(p);
}
__device__ __forceinline__ void cpasync16(uint32_t dst, const void* src) {
    asm volatile("cp.async.cg.shared.global [%0], [%1], 16;" :: "r"(dst), "l"(src));
}
__device__ __forceinline__ uint32_t swz(uint32_t off) { return off ^ ((off >> 3) & 0x70); }
__device__ __forceinline__ void ldsm4(uint32_t* r, uint32_t addr) {
    asm volatile("ldmatrix.sync.aligned.m8n8.x4.shared.b16 {%0,%1,%2,%3}, [%4];"
                 : "=r"(r[0]), "=r"(r[1]), "=r"(r[2]), "=r"(r[3]) : "r"(addr));
}
__device__ __forceinline__ void mma_f16(float* d, const uint32_t* a, const uint32_t* b) {
    asm volatile(
        "mma.sync.aligned.m16n8k16.row.col.f32.f16.f16.f32 "
        "{%0,%1,%2,%3}, {%4,%5,%6,%7}, {%8,%9}, {%0,%1,%2,%3};"
        : "+f"(d[0]), "+f"(d[1]), "+f"(d[2]), "+f"(d[3])
        : "r"(a[0]), "r"(a[1]), "r"(a[2]), "r"(a[3]), "r"(b[0]), "r"(b[1]));
}

// ================= prep kernels =================
__global__ void prep_kernel(const float* __restrict__ W1, const float* __restrict__ b1,
                            const float* __restrict__ b2) {
    int i = blockIdx.x * blockDim.x + threadIdx.x;  // 0..32767
    int k = i >> 8, n = i & 255;
    if (i < NIN * HPAD)
        g_W1p[i] = (n < 250) ? W1[k * 250 + n] : 0.0f;
    if (i < HPAD) {
        g_b1p[i] = (i < 250) ? b1[i] : 0.0f;
        g_b2p[i] = (i < 250) ? b2[i] : 0.0f;
    }
}
// W2h[n][c*64+kk] = split_{c%2}(W2[(c/2)*64+kk][n]); 2-term fp16 split
__global__ void prep_w2h_kernel(const float* __restrict__ W2) {
    int id = blockIdx.x * blockDim.x + threadIdx.x;  // 0..131071
    int n = id / KCAT2, kp = id % KCAT2;
    int c = kp >> 6, kk = kp & 63;
    int katom = c >> 1, split = c & 1;
    int k = katom * 64 + kk;
    float w = (k < 250 && n < 250) ? W2[k * 250 + n] : 0.0f;
    __half hi = __float2half_rn(w);
    float r1 = w - __half2float(hi);
    __half lo = __float2half_rn(r1);
    g_W2h[id] = (split == 0) ? hi : lo;
}

// ================= packed f32x2 helpers for layer-1 SGEMM =================
__device__ __forceinline__ void ffma2(unsigned long long& d, unsigned long long a,
                                      unsigned long long b) {
    asm("fma.rn.f32x2 %0, %1, %2, %0;" : "+l"(d) : "l"(a), "l"(b));
}
__device__ __forceinline__ unsigned long long dup2(float v) {
    unsigned long long r;
    unsigned int u = __float_as_uint(v);
    asm("mov.b64 %0, {%1, %1};" : "=l"(r) : "r"(u));
    return r;
}
__device__ __forceinline__ float2 unpack2(unsigned long long v) {
    float2 f;
    asm("mov.b64 {%0, %1}, %2;" : "=f"(f.x), "=f"(f.y) : "l"(v));
    return f;
}

// ---- layer-1 fp32 SGEMM (FFMA2), software-pipelined, K=128 ----
// C[M,256] = A[M,128] @ W[128,256] + bias
#define BM 128
#define BN 128
#define BK 16
#define NCH1 (NIN / BK)   // 8 chunks

__global__ __launch_bounds__(256, 2)
void sgemm_kernel(const float* __restrict__ A, const float* __restrict__ W,
                  const float* __restrict__ bias, float* __restrict__ C) {
    __shared__ __align__(16) float As[2][BK][BM];
    __shared__ __align__(16) float Ws[2][BK][BN];
    const int tid = threadIdx.x;
    const size_t m0 = (size_t)blockIdx.x * BM;
    const int n0 = blockIdx.y * BN;
    const int tr = tid >> 4, tc = tid & 15;
    const int aRow = tid >> 1, aCol = (tid & 1) * 8;
    const int wRow = tid >> 4, wCol = (tid & 15) * 8;

    unsigned long long acc[8][4];
#pragma unroll
    for (int i = 0; i < 8; i++)
#pragma unroll
        for (int jj = 0; jj < 4; jj++) acc[i][jj] = 0ULL;

    const float* Abase = A + (m0 + aRow) * (size_t)NIN + aCol;
    const float* Wbase = W + (size_t)wRow * HPAD + n0 + wCol;
    const uint32_t ws_s0 = smem_u32(&Ws[0][wRow][wCol]);
    const uint32_t ws_s1 = smem_u32(&Ws[1][wRow][wCol]);

    // prologue: W(0) via cp.async, A(0) into regs
    cpasync16(ws_s0, Wbase);
    cpasync16(ws_s0 + 16, Wbase + 4);
    asm volatile("cp.async.commit_group;" ::: "memory");
    float4 av0 = *(const float4*)(Abase);
    float4 av1 = *(const float4*)(Abase + 4);

#pragma unroll 1
    for (int c = 0; c < NCH1; c++) {
        const int buf = c & 1;
        // store A(c) (transposed) into As[buf]
        As[buf][aCol + 0][aRow] = av0.x; As[buf][aCol + 1][aRow] = av0.y;
        As[buf][aCol + 2][aRow] = av0.z; As[buf][aCol + 3][aRow] = av0.w;
        As[buf][aCol + 4][aRow] = av1.x; As[buf][aCol + 5][aRow] = av1.y;
        As[buf][aCol + 6][aRow] = av1.z; As[buf][aCol + 7][aRow] = av1.w;
        // W(c) cp.async complete (this thread), then publish via barrier
        asm volatile("cp.async.wait_group 0;" ::: "memory");
        __syncthreads();
        // issue next chunk's loads (overlapped with compute below)
        if (c < NCH1 - 1) {
            const uint32_t wd = (buf ? ws_s0 : ws_s1);
            const float* wsrc = Wbase + (size_t)(c + 1) * BK * HPAD;
            cpasync16(wd, wsrc);
            cpasync16(wd + 16, wsrc + 4);
            asm volatile("cp.async.commit_group;" ::: "memory");
            av0 = *(const float4*)(Abase + (c + 1) * BK);
            av1 = *(const float4*)(Abase + (c + 1) * BK + 4);
        }
        // compute chunk c (identical order to R7)
#pragma unroll
        for (int k = 0; k < BK; k++) {
            float ra[8];
            *(float4*)(&ra[0]) = *(const float4*)(&As[buf][k][tr * 8]);
            *(float4*)(&ra[4]) = *(const float4*)(&As[buf][k][tr * 8 + 4]);
            unsigned long long rb[4];
            rb[0] = *(const unsigned long long*)(&Ws[buf][k][tc * 4]);
            rb[1] = *(const unsigned long long*)(&Ws[buf][k][tc * 4 + 2]);
            rb[2] = *(const unsigned long long*)(&Ws[buf][k][64 + tc * 4]);
            rb[3] = *(const unsigned long long*)(&Ws[buf][k][64 + tc * 4 + 2]);
#pragma unroll
            for (int i = 0; i < 8; i++) {
                unsigned long long aa = dup2(ra[i]);
                ffma2(acc[i][0], aa, rb[0]);
                ffma2(acc[i][1], aa, rb[1]);
                ffma2(acc[i][2], aa, rb[2]);
                ffma2(acc[i][3], aa, rb[3]);
            }
        }
    }

    const int nA = n0 + tc * 4, nB = n0 + 64 + tc * 4;
    float4 bvA = *(const float4*)(bias + nA);
    float4 bvB = *(const float4*)(bias + nB);
#pragma unroll
    for (int i = 0; i < 8; i++) {
        size_t rowOff = (m0 + tr * 8 + i) * (size_t)HPAD;
        float2 p0 = unpack2(acc[i][0]), p1 = unpack2(acc[i][1]);
        float2 p2 = unpack2(acc[i][2]), p3 = unpack2(acc[i][3]);
        float4 cA = {p0.x + bvA.x, p0.y + bvA.y, p1.x + bvA.z, p1.y + bvA.w};
        float4 cB = {p2.x + bvB.x, p2.y + bvB.y, p3.x + bvB.z, p3.y + bvB.w};
        *(float4*)(C + rowOff + nA) = cA;
        *(float4*)(C + rowOff + nB) = cB;
    }
}

// ================= layer-2 GEMM via mma.sync fp16 (2-split, K=512) =================
#define OFF_A0 0
#define OFF_A1 16384
#define OFF_B0 32768
#define OFF_B1 49152
#define G2_SMEM 65536
#define NCHUNK 8

__global__ __launch_bounds__(256, 2)
void gemm2_mma_kernel(const __half* __restrict__ s1h,
                      const __half* __restrict__ W2h,
                      float* __restrict__ out) {
    extern __shared__ __align__(1024) char smem[];
    const uint32_t sb = smem_u32(smem);
    const int tid = threadIdx.x;
    const int warp = tid >> 5, lane = tid & 31;
    const int g = lane >> 2, tig = lane & 3;
    const int wm = warp >> 2, wn = warp & 3;
    const size_t m0 = (size_t)blockIdx.x * 128;
    const int n0 = blockIdx.y * 128;

    const int ldr = tid >> 1;
    const int ldh = tid & 1;

    const int arow_l = lane & 15, ahalf = lane >> 4;
    const uint32_t a_off0 = (uint32_t)((wm * 64 + arow_l) * 128 + ahalf * 16);
    const int lane8 = lane & 7, laneg = lane >> 3;
    const uint32_t b_off0 =
        (uint32_t)((wn * 32 + ((laneg & 2) ? 8 : 0) + lane8) * 128 + (laneg & 1) * 16);

    float acc[4][4][4];
#pragma unroll
    for (int mf = 0; mf < 4; mf++)
#pragma unroll
        for (int nf = 0; nf < 4; nf++)
#pragma unroll
            for (int q = 0; q < 4; q++) acc[mf][nf][q] = 0.0f;

    const __half* asrc = s1h + (m0 + ldr) * HPAD + ldh * 32;
    const __half* bsrc = W2h + (size_t)(n0 + ldr) * KCAT2 + ldh * 32;
    const uint32_t ldst = swz((uint32_t)(ldr * 128 + ldh * 64));

#pragma unroll
    for (int j = 0; j < 4; j++) cpasync16(sb + OFF_A0 + (ldst ^ (j * 16)), asrc + j * 8);
#pragma unroll
    for (int j = 0; j < 4; j++) cpasync16(sb + OFF_B0 + (ldst ^ (j * 16)), bsrc + j * 8);
    asm volatile("cp.async.commit_group;" ::: "memory");

#pragma unroll 1
    for (int c = 0; c < NCHUNK; c++) {
        if (c < NCHUNK - 1) {
            const int cn = c + 1;
            if ((cn & 1) == 0) {
                const uint32_t ab = sb + (((cn >> 1) & 1) ? OFF_A1 : OFF_A0);
                const __half* src = asrc + (cn >> 1) * 64;
#pragma unroll
                for (int j = 0; j < 4; j++) cpasync16(ab + (ldst ^ (j * 16)), src + j * 8);
            }
            const uint32_t bb = sb + ((cn & 1) ? OFF_B1 : OFF_B0);
            const __half* src = bsrc + cn * 64;
#pragma unroll
            for (int j = 0; j < 4; j++) cpasync16(bb + (ldst ^ (j * 16)), src + j * 8);
            asm volatile("cp.async.commit_group;" ::: "memory");
            asm volatile("cp.async.wait_group 1;" ::: "memory");
        } else {
            asm volatile("cp.async.wait_group 0;" ::: "memory");
        }
        __syncthreads();

        const uint32_t ab = sb + (((c >> 1) & 1) ? OFF_A1 : OFF_A0);
        const uint32_t bb = sb + ((c & 1) ? OFF_B1 : OFF_B0);
#pragma unroll
        for (int ks = 0; ks < 4; ks++) {
            uint32_t afr[4][4];
#pragma unroll
            for (int mf = 0; mf < 4; mf++)
                ldsm4(afr[mf], ab + swz(a_off0 + (uint32_t)(mf * 16 * 128 + ks * 32)));
            uint32_t bfr[4][2];
            ldsm4(&bfr[0][0], bb + swz(b_off0 + (uint32_t)(ks * 32)));
            ldsm4(&bfr[2][0], bb + swz(b_off0 + (uint32_t)(16 * 128 + ks * 32)));
#pragma unroll
            for (int mf = 0; mf < 4; mf++)
#pragma unroll
                for (int nf = 0; nf < 4; nf++)
                    mma_f16(acc[mf][nf], afr[mf], bfr[nf]);
        }
        __syncthreads();
    }

#pragma unroll
    for (int mf = 0; mf < 4; mf++) {
        size_t r0 = (m0 + wm * 64 + mf * 16 + g) * HPAD;
#pragma unroll
        for (int nf = 0; nf < 4; nf++) {
            int col = n0 + wn * 32 + nf * 8 + tig * 2;
            *(float2*)(out + r0 + col) = make_float2(acc[mf][nf][0], acc[mf][nf][1]);
            *(float2*)(out + r0 + 8 * HPAD + col) = make_float2(acc[mf][nf][2], acc[mf][nf][3]);
        }
    }
}

// ================= LIF scans (1 lane per thread) =================
__global__ void lif_scan1_kernel(const float* __restrict__ buf,
                                 __half* __restrict__ s1h) {
    int lane = blockIdx.x * blockDim.x + threadIdx.x;  // 0..131071
    float m = 0.0f;
    size_t idx = lane;
#pragma unroll 8
    for (int t = 0; t < T_STEPS; t++) {
        float cur = buf[idx];
        float r = (m > 1.0f) ? 1.0f : 0.0f;
        m = __fadd_rn(__fadd_rn(__fmul_rn(0.9f, m), cur), -r);
        s1h[idx] = __float2half((m > 1.0f) ? 1.0f : 0.0f);
        idx += LANES;
    }
}
__global__ void lif_scan2_kernel(const float* __restrict__ buf,
                                 const float* __restrict__ bias,
                                 __half* __restrict__ s2h) {
    int lane = blockIdx.x * blockDim.x + threadIdx.x;
    float bv = bias[lane & 255];
    float m = 0.0f;
    size_t idx = lane;
#pragma unroll 8
    for (int t = 0; t < T_STEPS; t++) {
        float cur = __fadd_rn(buf[idx], bv);
        float r = (m > 1.0f) ? 1.0f : 0.0f;
        m = __fadd_rn(__fadd_rn(__fmul_rn(0.9f, m), cur), -r);
        s2h[idx] = __float2half((m > 1.0f) ? 1.0f : 0.0f);
        idx += LANES;
    }
}

// ---- layer 3 GEMM: warp-per-row dot over fp16 spikes, N=2, K=256 (pad cols = 0) ----
__global__ __launch_bounds__(256)
void gemm3_kernel(const __half* __restrict__ S2, const float* __restrict__ W3,
                  const float* __restrict__ b3, float* __restrict__ cur3) {
    __shared__ float w0[HPAD], w1[HPAD];
    int tid = threadIdx.x;
    if (tid < 250) { w0[tid] = W3[tid * 2]; w1[tid] = W3[tid * 2 + 1]; }
    else           { w0[tid] = 0.0f;        w1[tid] = 0.0f; }
    __syncthreads();
    int warp = tid >> 5, lane = tid & 31;
    size_t row = (size_t)blockIdx.x * 8 + warp;
    const uint4* p = (const uint4*)(S2 + row * HPAD);
    uint4 v = p[lane];
    const __half2* h = (const __half2*)&v;
    float a0 = 0.0f, a1 = 0.0f;
    int k0 = lane * 8;
#pragma unroll
    for (int j = 0; j < 4; j++) {
        float2 f = __half22float2(h[j]);
        int k = k0 + j * 2;
        a0 = fmaf(f.x, w0[k], a0); a0 = fmaf(f.y, w0[k + 1], a0);
        a1 = fmaf(f.x, w1[k], a1); a1 = fmaf(f.y, w1[k + 1], a1);
    }
#pragma unroll
    for (int off = 16; off; off >>= 1) {
        a0 += __shfl_xor_sync(0xffffffffu, a0, off);
        a1 += __shfl_xor_sync(0xffffffffu, a1, off);
    }
    if (lane == 0) {
        cur3[row * 2 + 0] = a0 + b3[0];
        cur3[row * 2 + 1] = a1 + b3[1];
    }
}

__global__ void lif3_kernel(const float* __restrict__ cur3, float* __restrict__ out) {
    int lane = blockIdx.x * blockDim.x + threadIdx.x;
    float m = 0.0f;
#pragma unroll 16
    for (int t = 0; t < T_STEPS; t++) {
        float cur = cur3[t * 1024 + lane];
        float r = (m > 1.0f) ? 1.0f : 0.0f;
        m = __fadd_rn(__fadd_rn(__fmul_rn(0.9f, m), cur), -r);
        out[t * 1024 + lane] = (m > 1.0f) ? 1.0f : 0.0f;
        out[OUTB + t * 1024 + lane] = m;
    }
}

extern "C" void kernel_launch(void* const* d_in, const int* in_sizes, int n_in,
                              void* d_out, int out_size) {
    const float* x  = (const float*)d_in[0];
    const float* W1 = (const float*)d_in[1];
    const float* b1 = (const float*)d_in[2];
    const float* W2 = (const float*)d_in[3];
    const float* b2 = (const float*)d_in[4];
    const float* W3 = (const float*)d_in[5];
    const float* b3 = (const float*)d_in[6];
    float* out = (float*)d_out;

    float *buf1, *buf2, *cur3, *W1p, *b1p, *b2p;
    __half *s1h, *s2h, *W2h;
    cudaGetSymbolAddress((void**)&buf1, g_buf1);
    cudaGetSymbolAddress((void**)&buf2, g_buf2);
    cudaGetSymbolAddress((void**)&cur3, g_cur3);
    cudaGetSymbolAddress((void**)&W1p, g_W1p);
    cudaGetSymbolAddress((void**)&b1p, g_b1p);
    cudaGetSymbolAddress((void**)&b2p, g_b2p);
    cudaGetSymbolAddress((void**)&s1h, g_s1h);
    cudaGetSymbolAddress((void**)&s2h, g_s2h);
    cudaGetSymbolAddress((void**)&W2h, g_W2h);

    cudaFuncSetAttribute(gemm2_mma_kernel,
                         cudaFuncAttributeMaxDynamicSharedMemorySize, G2_SMEM);

    prep_kernel<<<128, 256>>>(W1, b1, b2);
    prep_w2h_kernel<<<512, 256>>>(W2);

    // layer 1: cur1 = x @ W1 + b1 (exact FFMA2 fp32, pipelined)
    sgemm_kernel<<<dim3(MROWS / BM, HPAD / BN), 256>>>(x, W1p, b1p, buf1);
    lif_scan1_kernel<<<LANES / 256, 256>>>(buf1, s1h);

    // layer 2: cur2 = s1 @ (W2hi + W2lo) via fp16 mma.sync (K=512); bias in scan
    gemm2_mma_kernel<<<dim3(MROWS / 128, 2), 256, G2_SMEM>>>(s1h, W2h, buf2);
    lif_scan2_kernel<<<LANES / 256, 256>>>(buf2, b2p, s2h);

    // layer 3
    gemm3_kernel<<<MROWS / 8, 256>>>(s2h, W3, b3, cur3);
    lif3_kernel<<<4, 256>>>(cur3, out);
}

// round 15
// speedup vs baseline: 1.1846x; 1.0724x over previous
#include <cuda_runtime.h>
#include <cuda_fp16.h>
#include <cstdint>

#define T_STEPS 1000
#define BATCH   512
#define NIN     128
#define HPAD    256
#define KCAT2   512                   // 2 fp16 splits x 256
#define LANES   (BATCH * HPAD)        // 131072
#define MROWS   (T_STEPS * BATCH)     // 512000
#define OUTB    (T_STEPS * BATCH * 2) // 1024000

// ---- scratch (static device memory; no allocations allowed) ----
__device__ float g_buf1[(size_t)MROWS * HPAD];   // cur1 (fp32, bias included)
__device__ __half g_s1h[(size_t)MROWS * HPAD];   // s1 spikes fp16
__device__ float g_buf2[(size_t)MROWS * HPAD];   // cur2 raw fp32
__device__ uint32_t g_s2bits[(size_t)MROWS * 8]; // s2 spikes, 1 bit per lane
__device__ float g_cur3[(size_t)MROWS * 2];
__device__ float g_W1p[NIN * HPAD];
__device__ float g_b1p[HPAD];
__device__ float g_b2p[HPAD];
__device__ __half g_W2h[HPAD * KCAT2];  // [n=256][k'=512], 2-split fp16 per katom

// ================= helpers =================
__device__ __forceinline__ uint32_t smem_u32(const void* p) {
    return (uint32_t)__cvta_generic_to_shared(p);
}
__device__ __forceinline__ void cpasync16(uint32_t dst, const void* src) {
    asm volatile("cp.async.cg.shared.global [%0], [%1], 16;" :: "r"(dst), "l"(src));
}
__device__ __forceinline__ uint32_t swz(uint32_t off) { return off ^ ((off >> 3) & 0x70); }
__device__ __forceinline__ void ldsm4(uint32_t* r, uint32_t addr) {
    asm volatile("ldmatrix.sync.aligned.m8n8.x4.shared.b16 {%0,%1,%2,%3}, [%4];"
                 : "=r"(r[0]), "=r"(r[1]), "=r"(r[2]), "=r"(r[3]) : "r"(addr));
}
__device__ __forceinline__ void mma_f16(float* d, const uint32_t* a, const uint32_t* b) {
    asm volatile(
        "mma.sync.aligned.m16n8k16.row.col.f32.f16.f16.f32 "
        "{%0,%1,%2,%3}, {%4,%5,%6,%7}, {%8,%9}, {%0,%1,%2,%3};"
        : "+f"(d[0]), "+f"(d[1]), "+f"(d[2]), "+f"(d[3])
        : "r"(a[0]), "r"(a[1]), "r"(a[2]), "r"(a[3]), "r"(b[0]), "r"(b[1]));
}

// ================= prep kernels =================
__global__ void prep_kernel(const float* __restrict__ W1, const float* __restrict__ b1,
                            const float* __restrict__ b2) {
    int i = blockIdx.x * blockDim.x + threadIdx.x;  // 0..32767
    int k = i >> 8, n = i & 255;
    if (i < NIN * HPAD)
        g_W1p[i] = (n < 250) ? W1[k * 250 + n] : 0.0f;
    if (i < HPAD) {
        g_b1p[i] = (i < 250) ? b1[i] : 0.0f;
        g_b2p[i] = (i < 250) ? b2[i] : 0.0f;
    }
}
// W2h[n][c*64+kk] = split_{c%2}(W2[(c/2)*64+kk][n]); 2-term fp16 split
__global__ void prep_w2h_kernel(const float* __restrict__ W2) {
    int id = blockIdx.x * blockDim.x + threadIdx.x;  // 0..131071
    int n = id / KCAT2, kp = id % KCAT2;
    int c = kp >> 6, kk = kp & 63;
    int katom = c >> 1, split = c & 1;
    int k = katom * 64 + kk;
    float w = (k < 250 && n < 250) ? W2[k * 250 + n] : 0.0f;
    __half hi = __float2half_rn(w);
    float r1 = w - __half2float(hi);
    __half lo = __float2half_rn(r1);
    g_W2h[id] = (split == 0) ? hi : lo;
}

// ================= packed f32x2 helpers for layer-1 SGEMM =================
__device__ __forceinline__ void ffma2(unsigned long long& d, unsigned long long a,
                                      unsigned long long b) {
    asm("fma.rn.f32x2 %0, %1, %2, %0;" : "+l"(d) : "l"(a), "l"(b));
}
__device__ __forceinline__ unsigned long long dup2(float v) {
    unsigned long long r;
    unsigned int u = __float_as_uint(v);
    asm("mov.b64 %0, {%1, %1};" : "=l"(r) : "r"(u));
    return r;
}
__device__ __forceinline__ float2 unpack2(unsigned long long v) {
    float2 f;
    asm("mov.b64 {%0, %1}, %2;" : "=f"(f.x), "=f"(f.y) : "l"(v));
    return f;
}

// ---- layer-1 fp32 SGEMM (FFMA2), software-pipelined, K=128 ----
// C[M,256] = A[M,128] @ W[128,256] + bias ; grid (2, 4000): x = N-tile, y = M-tile
#define BM 128
#define BN 128
#define BK 16
#define NCH1 (NIN / BK)   // 8 chunks

__global__ __launch_bounds__(256, 2)
void sgemm_kernel(const float* __restrict__ A, const float* __restrict__ W,
                  const float* __restrict__ bias, float* __restrict__ C) {
    __shared__ __align__(16) float As[2][BK][BM];
    __shared__ __align__(16) float Ws[2][BK][BN];
    const int tid = threadIdx.x;
    const size_t m0 = (size_t)blockIdx.y * BM;
    const int n0 = blockIdx.x * BN;
    const int tr = tid >> 4, tc = tid & 15;
    const int aRow = tid >> 1, aCol = (tid & 1) * 8;
    const int wRow = tid >> 4, wCol = (tid & 15) * 8;

    unsigned long long acc[8][4];
#pragma unroll
    for (int i = 0; i < 8; i++)
#pragma unroll
        for (int jj = 0; jj < 4; jj++) acc[i][jj] = 0ULL;

    const float* Abase = A + (m0 + aRow) * (size_t)NIN + aCol;
    const float* Wbase = W + (size_t)wRow * HPAD + n0 + wCol;
    const uint32_t ws_s0 = smem_u32(&Ws[0][wRow][wCol]);
    const uint32_t ws_s1 = smem_u32(&Ws[1][wRow][wCol]);

    // prologue: W(0) via cp.async, A(0) into regs
    cpasync16(ws_s0, Wbase);
    cpasync16(ws_s0 + 16, Wbase + 4);
    asm volatile("cp.async.commit_group;" ::: "memory");
    float4 av0 = *(const float4*)(Abase);
    float4 av1 = *(const float4*)(Abase + 4);

#pragma unroll 1
    for (int c = 0; c < NCH1; c++) {
        const int buf = c & 1;
        As[buf][aCol + 0][aRow] = av0.x; As[buf][aCol + 1][aRow] = av0.y;
        As[buf][aCol + 2][aRow] = av0.z; As[buf][aCol + 3][aRow] = av0.w;
        As[buf][aCol + 4][aRow] = av1.x; As[buf][aCol + 5][aRow] = av1.y;
        As[buf][aCol + 6][aRow] = av1.z; As[buf][aCol + 7][aRow] = av1.w;
        asm volatile("cp.async.wait_group 0;" ::: "memory");
        __syncthreads();
        if (c < NCH1 - 1) {
            const uint32_t wd = (buf ? ws_s0 : ws_s1);
            const float* wsrc = Wbase + (size_t)(c + 1) * BK * HPAD;
            cpasync16(wd, wsrc);
            cpasync16(wd + 16, wsrc + 4);
            asm volatile("cp.async.commit_group;" ::: "memory");
            av0 = *(const float4*)(Abase + (c + 1) * BK);
            av1 = *(const float4*)(Abase + (c + 1) * BK + 4);
        }
#pragma unroll
        for (int k = 0; k < BK; k++) {
            float ra[8];
            *(float4*)(&ra[0]) = *(const float4*)(&As[buf][k][tr * 8]);
            *(float4*)(&ra[4]) = *(const float4*)(&As[buf][k][tr * 8 + 4]);
            unsigned long long rb[4];
            rb[0] = *(const unsigned long long*)(&Ws[buf][k][tc * 4]);
            rb[1] = *(const unsigned long long*)(&Ws[buf][k][tc * 4 + 2]);
            rb[2] = *(const unsigned long long*)(&Ws[buf][k][64 + tc * 4]);
            rb[3] = *(const unsigned long long*)(&Ws[buf][k][64 + tc * 4 + 2]);
#pragma unroll
            for (int i = 0; i < 8; i++) {
                unsigned long long aa = dup2(ra[i]);
                ffma2(acc[i][0], aa, rb[0]);
                ffma2(acc[i][1], aa, rb[1]);
                ffma2(acc[i][2], aa, rb[2]);
                ffma2(acc[i][3], aa, rb[3]);
            }
        }
    }

    const int nA = n0 + tc * 4, nB = n0 + 64 + tc * 4;
    float4 bvA = *(const float4*)(bias + nA);
    float4 bvB = *(const float4*)(bias + nB);
#pragma unroll
    for (int i = 0; i < 8; i++) {
        size_t rowOff = (m0 + tr * 8 + i) * (size_t)HPAD;
        float2 p0 = unpack2(acc[i][0]), p1 = unpack2(acc[i][1]);
        float2 p2 = unpack2(acc[i][2]), p3 = unpack2(acc[i][3]);
        float4 cA = {p0.x + bvA.x, p0.y + bvA.y, p1.x + bvA.z, p1.y + bvA.w};
        float4 cB = {p2.x + bvB.x, p2.y + bvB.y, p3.x + bvB.z, p3.y + bvB.w};
        *(float4*)(C + rowOff + nA) = cA;
        *(float4*)(C + rowOff + nB) = cB;
    }
}

// ================= layer-2 GEMM via mma.sync fp16 (2-split, K=512) =================
// grid (2, 4000): x = N-tile, y = M-tile (adjacent bids share the A tile via L2)
#define OFF_A0 0
#define OFF_A1 16384
#define OFF_B0 32768
#define OFF_B1 49152
#define G2_SMEM 65536
#define NCHUNK 8

__global__ __launch_bounds__(256, 2)
void gemm2_mma_kernel(const __half* __restrict__ s1h,
                      const __half* __restrict__ W2h,
                      float* __restrict__ out) {
    extern __shared__ __align__(1024) char smem[];
    const uint32_t sb = smem_u32(smem);
    const int tid = threadIdx.x;
    const int warp = tid >> 5, lane = tid & 31;
    const int g = lane >> 2, tig = lane & 3;
    const int wm = warp >> 2, wn = warp & 3;
    const size_t m0 = (size_t)blockIdx.y * 128;
    const int n0 = blockIdx.x * 128;

    const int ldr = tid >> 1;
    const int ldh = tid & 1;

    const int arow_l = lane & 15, ahalf = lane >> 4;
    const uint32_t a_off0 = (uint32_t)((wm * 64 + arow_l) * 128 + ahalf * 16);
    const int lane8 = lane & 7, laneg = lane >> 3;
    const uint32_t b_off0 =
        (uint32_t)((wn * 32 + ((laneg & 2) ? 8 : 0) + lane8) * 128 + (laneg & 1) * 16);

    float acc[4][4][4];
#pragma unroll
    for (int mf = 0; mf < 4; mf++)
#pragma unroll
        for (int nf = 0; nf < 4; nf++)
#pragma unroll
            for (int q = 0; q < 4; q++) acc[mf][nf][q] = 0.0f;

    const __half* asrc = s1h + (m0 + ldr) * HPAD + ldh * 32;
    const __half* bsrc = W2h + (size_t)(n0 + ldr) * KCAT2 + ldh * 32;
    const uint32_t ldst = swz((uint32_t)(ldr * 128 + ldh * 64));

#pragma unroll
    for (int j = 0; j < 4; j++) cpasync16(sb + OFF_A0 + (ldst ^ (j * 16)), asrc + j * 8);
#pragma unroll
    for (int j = 0; j < 4; j++) cpasync16(sb + OFF_B0 + (ldst ^ (j * 16)), bsrc + j * 8);
    asm volatile("cp.async.commit_group;" ::: "memory");

#pragma unroll 1
    for (int c = 0; c < NCHUNK; c++) {
        if (c < NCHUNK - 1) {
            const int cn = c + 1;
            if ((cn & 1) == 0) {
                const uint32_t ab = sb + (((cn >> 1) & 1) ? OFF_A1 : OFF_A0);
                const __half* src = asrc + (cn >> 1) * 64;
#pragma unroll
                for (int j = 0; j < 4; j++) cpasync16(ab + (ldst ^ (j * 16)), src + j * 8);
            }
            const uint32_t bb = sb + ((cn & 1) ? OFF_B1 : OFF_B0);
            const __half* src = bsrc + cn * 64;
#pragma unroll
            for (int j = 0; j < 4; j++) cpasync16(bb + (ldst ^ (j * 16)), src + j * 8);
            asm volatile("cp.async.commit_group;" ::: "memory");
            asm volatile("cp.async.wait_group 1;" ::: "memory");
        } else {
            asm volatile("cp.async.wait_group 0;" ::: "memory");
        }
        __syncthreads();

        const uint32_t ab = sb + (((c >> 1) & 1) ? OFF_A1 : OFF_A0);
        const uint32_t bb = sb + ((c & 1) ? OFF_B1 : OFF_B0);
#pragma unroll
        for (int ks = 0; ks < 4; ks++) {
            uint32_t afr[4][4];
#pragma unroll
            for (int mf = 0; mf < 4; mf++)
                ldsm4(afr[mf], ab + swz(a_off0 + (uint32_t)(mf * 16 * 128 + ks * 32)));
            uint32_t bfr[4][2];
            ldsm4(&bfr[0][0], bb + swz(b_off0 + (uint32_t)(ks * 32)));
            ldsm4(&bfr[2][0], bb + swz(b_off0 + (uint32_t)(16 * 128 + ks * 32)));
#pragma unroll
            for (int mf = 0; mf < 4; mf++)
#pragma unroll
                for (int nf = 0; nf < 4; nf++)
                    mma_f16(acc[mf][nf], afr[mf], bfr[nf]);
        }
        __syncthreads();
    }

#pragma unroll
    for (int mf = 0; mf < 4; mf++) {
        size_t r0 = (m0 + wm * 64 + mf * 16 + g) * HPAD;
#pragma unroll
        for (int nf = 0; nf < 4; nf++) {
            int col = n0 + wn * 32 + nf * 8 + tig * 2;
            *(float2*)(out + r0 + col) = make_float2(acc[mf][nf][0], acc[mf][nf][1]);
            *(float2*)(out + r0 + 8 * HPAD + col) = make_float2(acc[mf][nf][2], acc[mf][nf][3]);
        }
    }
}

// ================= LIF scans (1 lane per thread) =================
__global__ void lif_scan1_kernel(const float* __restrict__ buf,
                                 __half* __restrict__ s1h) {
    int lane = blockIdx.x * blockDim.x + threadIdx.x;  // 0..131071
    float m = 0.0f;
    size_t idx = lane;
#pragma unroll 8
    for (int t = 0; t < T_STEPS; t++) {
        float cur = buf[idx];
        float r = (m > 1.0f) ? 1.0f : 0.0f;
        m = __fadd_rn(__fadd_rn(__fmul_rn(0.9f, m), cur), -r);
        s1h[idx] = __float2half((m > 1.0f) ? 1.0f : 0.0f);
        idx += LANES;
    }
}
// layer 2 scan: add bias, write spikes as bitmask (1 bit per lane via ballot)
__global__ void lif_scan2_kernel(const float* __restrict__ buf,
                                 const float* __restrict__ bias,
                                 uint32_t* __restrict__ s2bits) {
    int id = blockIdx.x * blockDim.x + threadIdx.x;  // 0..131071
    int lane = id & 31;
    int word = id >> 5;                              // 0..4095
    float bv = bias[id & 255];
    float m = 0.0f;
    size_t idx = id;
#pragma unroll 8
    for (int t = 0; t < T_STEPS; t++) {
        float cur = __fadd_rn(buf[idx], bv);
        float r = (m > 1.0f) ? 1.0f : 0.0f;
        m = __fadd_rn(__fadd_rn(__fmul_rn(0.9f, m), cur), -r);
        uint32_t bal = __ballot_sync(0xffffffffu, m > 1.0f);
        if (lane == 0) s2bits[(size_t)t * (LANES / 32) + word] = bal;
        idx += LANES;
    }
}

// ---- layer 3 GEMM over spike bitmask: warp-per-row, N=2, K=256 ----
// lane handles h = lane*8 .. lane*8+7 (same mapping/order as fp16 version)
__global__ __launch_bounds__(256)
void gemm3_kernel(const uint32_t* __restrict__ s2bits, const float* __restrict__ W3,
                  const float* __restrict__ b3, float* __restrict__ cur3) {
    __shared__ float w0[HPAD], w1[HPAD];
    int tid = threadIdx.x;
    if (tid < 250) { w0[tid] = W3[tid * 2]; w1[tid] = W3[tid * 2 + 1]; }
    else           { w0[tid] = 0.0f;        w1[tid] = 0.0f; }
    __syncthreads();
    int warp = tid >> 5, lane = tid & 31;
    size_t row = (size_t)blockIdx.x * 8 + warp;
    uint32_t wbits = __ldg(s2bits + row * 8 + (lane >> 2));
    uint32_t byte = (wbits >> ((lane & 3) * 8)) & 0xFFu;
    float a0 = 0.0f, a1 = 0.0f;
    int k0 = lane * 8;
#pragma unroll
    for (int j = 0; j < 8; j++) {
        if (byte & (1u << j)) {
            a0 += w0[k0 + j];
            a1 += w1[k0 + j];
        }
    }
#pragma unroll
    for (int off = 16; off; off >>= 1) {
        a0 += __shfl_xor_sync(0xffffffffu, a0, off);
        a1 += __shfl_xor_sync(0xffffffffu, a1, off);
    }
    if (lane == 0) {
        cur3[row * 2 + 0] = a0 + b3[0];
        cur3[row * 2 + 1] = a1 + b3[1];
    }
}

__global__ void lif3_kernel(const float* __restrict__ cur3, float* __restrict__ out) {
    int lane = blockIdx.x * blockDim.x + threadIdx.x;
    float m = 0.0f;
#pragma unroll 16
    for (int t = 0; t < T_STEPS; t++) {
        float cur = cur3[t * 1024 + lane];
        float r = (m > 1.0f) ? 1.0f : 0.0f;
        m = __fadd_rn(__fadd_rn(__fmul_rn(0.9f, m), cur), -r);
        out[t * 1024 + lane] = (m > 1.0f) ? 1.0f : 0.0f;
        out[OUTB + t * 1024 + lane] = m;
    }
}

extern "C" void kernel_launch(void* const* d_in, const int* in_sizes, int n_in,
                              void* d_out, int out_size) {
    const float* x  = (const float*)d_in[0];
    const float* W1 = (const float*)d_in[1];
    const float* b1 = (const float*)d_in[2];
    const float* W2 = (const float*)d_in[3];
    const float* b2 = (const float*)d_in[4];
    const float* W3 = (const float*)d_in[5];
    const float* b3 = (const float*)d_in[6];
    float* out = (float*)d_out;

    float *buf1, *buf2, *cur3, *W1p, *b1p, *b2p;
    __half *s1h, *W2h;
    uint32_t* s2bits;
    cudaGetSymbolAddress((void**)&buf1, g_buf1);
    cudaGetSymbolAddress((void**)&buf2, g_buf2);
    cudaGetSymbolAddress((void**)&cur3, g_cur3);
    cudaGetSymbolAddress((void**)&W1p, g_W1p);
    cudaGetSymbolAddress((void**)&b1p, g_b1p);
    cudaGetSymbolAddress((void**)&b2p, g_b2p);
    cudaGetSymbolAddress((void**)&s1h, g_s1h);
    cudaGetSymbolAddress((void**)&s2bits, g_s2bits);
    cudaGetSymbolAddress((void**)&W2h, g_W2h);

    cudaFuncSetAttribute(gemm2_mma_kernel,
                         cudaFuncAttributeMaxDynamicSharedMemorySize, G2_SMEM);

    prep_kernel<<<128, 256>>>(W1, b1, b2);
    prep_w2h_kernel<<<512, 256>>>(W2);

    // layer 1: cur1 = x @ W1 + b1 (exact FFMA2 fp32, pipelined; N-tiles adjacent)
    sgemm_kernel<<<dim3(HPAD / BN, MROWS / BM), 256>>>(x, W1p, b1p, buf1);
    lif_scan1_kernel<<<LANES / 256, 256>>>(buf1, s1h);

    // layer 2: cur2 = s1 @ (W2hi + W2lo) via fp16 mma.sync (K=512); bias in scan
    gemm2_mma_kernel<<<dim3(2, MROWS / 128), 256, G2_SMEM>>>(s1h, W2h, buf2);
    lif_scan2_kernel<<<LANES / 256, 256>>>(buf2, b2p, s2bits);

    // layer 3 over spike bitmask
    gemm3_kernel<<<MROWS / 8, 256>>>(s2bits, W3, b3, cur3);
    lif3_kernel<<<4, 256>>>(cur3, out);
}

// round 16
// speedup vs baseline: 1.2328x; 1.0408x over previous
#include <cuda_runtime.h>
#include <cuda_fp16.h>
#include <cstdint>

#define T_STEPS 1000
#define BATCH   512
#define NIN     128
#define HPAD    256
#define KCAT2   512                   // 2 fp16 splits x 256
#define LANES   (BATCH * HPAD)        // 131072
#define MROWS   (T_STEPS * BATCH)     // 512000
#define OUTB    (T_STEPS * BATCH * 2) // 1024000

// ---- scratch (static device memory; no allocations allowed) ----
__device__ float g_buf1[(size_t)MROWS * HPAD];   // cur1 (fp32, bias included)
__device__ uint32_t g_s1bits[(size_t)MROWS * 8]; // s1 spikes, 1 bit per lane
__device__ float g_buf2[(size_t)MROWS * HPAD];   // cur2 raw fp32
__device__ uint32_t g_s2bits[(size_t)MROWS * 8]; // s2 spikes, 1 bit per lane
__device__ float g_cur3[(size_t)MROWS * 2];
__device__ float g_W1p[NIN * HPAD];
__device__ float g_b1p[HPAD];
__device__ float g_b2p[HPAD];
__device__ __half g_W2h[HPAD * KCAT2];  // [n=256][k'=512], 2-split fp16 per katom

// ================= helpers =================
__device__ __forceinline__ uint32_t smem_u32(const void* p) {
    return (uint32_t)__cvta_generic_to_shared(p);
}
__device__ __forceinline__ void cpasync16(uint32_t dst, const void* src) {
    asm volatile("cp.async.cg.shared.global [%0], [%1], 16;" :: "r"(dst), "l"(src));
}
__device__ __forceinline__ uint32_t swz(uint32_t off) { return off ^ ((off >> 3) & 0x70); }
__device__ __forceinline__ void ldsm4(uint32_t* r, uint32_t addr) {
    asm volatile("ldmatrix.sync.aligned.m8n8.x4.shared.b16 {%0,%1,%2,%3}, [%4];"
                 : "=r"(r[0]), "=r"(r[1]), "=r"(r[2]), "=r"(r[3]) : "r"(addr));
}
__device__ __forceinline__ void mma_f16(float* d, const uint32_t* a, const uint32_t* b) {
    asm volatile(
        "mma.sync.aligned.m16n8k16.row.col.f32.f16.f16.f32 "
        "{%0,%1,%2,%3}, {%4,%5,%6,%7}, {%8,%9}, {%0,%1,%2,%3};"
        : "+f"(d[0]), "+f"(d[1]), "+f"(d[2]), "+f"(d[3])
        : "r"(a[0]), "r"(a[1]), "r"(a[2]), "r"(a[3]), "r"(b[0]), "r"(b[1]));
}

// ================= prep kernels =================
__global__ void prep_kernel(const float* __restrict__ W1, const float* __restrict__ b1,
                            const float* __restrict__ b2) {
    int i = blockIdx.x * blockDim.x + threadIdx.x;  // 0..32767
    int k = i >> 8, n = i & 255;
    if (i < NIN * HPAD)
        g_W1p[i] = (n < 250) ? W1[k * 250 + n] : 0.0f;
    if (i < HPAD) {
        g_b1p[i] = (i < 250) ? b1[i] : 0.0f;
        g_b2p[i] = (i < 250) ? b2[i] : 0.0f;
    }
}
// W2h[n][c*64+kk] = split_{c%2}(W2[(c/2)*64+kk][n]); 2-term fp16 split
__global__ void prep_w2h_kernel(const float* __restrict__ W2) {
    int id = blockIdx.x * blockDim.x + threadIdx.x;  // 0..131071
    int n = id / KCAT2, kp = id % KCAT2;
    int c = kp >> 6, kk = kp & 63;
    int katom = c >> 1, split = c & 1;
    int k = katom * 64 + kk;
    float w = (k < 250 && n < 250) ? W2[k * 250 + n] : 0.0f;
    __half hi = __float2half_rn(w);
    float r1 = w - __half2float(hi);
    __half lo = __float2half_rn(r1);
    g_W2h[id] = (split == 0) ? hi : lo;
}

// ================= packed f32x2 helpers for layer-1 SGEMM =================
__device__ __forceinline__ void ffma2(unsigned long long& d, unsigned long long a,
                                      unsigned long long b) {
    asm("fma.rn.f32x2 %0, %1, %2, %0;" : "+l"(d) : "l"(a), "l"(b));
}
__device__ __forceinline__ unsigned long long dup2(float v) {
    unsigned long long r;
    unsigned int u = __float_as_uint(v);
    asm("mov.b64 %0, {%1, %1};" : "=l"(r) : "r"(u));
    return r;
}
__device__ __forceinline__ float2 unpack2(unsigned long long v) {
    float2 f;
    asm("mov.b64 {%0, %1}, %2;" : "=f"(f.x), "=f"(f.y) : "l"(v));
    return f;
}

// ---- layer-1 fp32 SGEMM (FFMA2), software-pipelined, K=128 ----
// C[M,256] = A[M,128] @ W[128,256] + bias ; grid (2, 4000): x = N-tile, y = M-tile
#define BM 128
#define BN 128
#define BK 16
#define NCH1 (NIN / BK)   // 8 chunks

__global__ __launch_bounds__(256, 2)
void sgemm_kernel(const float* __restrict__ A, const float* __restrict__ W,
                  const float* __restrict__ bias, float* __restrict__ C) {
    __shared__ __align__(16) float As[2][BK][BM];
    __shared__ __align__(16) float Ws[2][BK][BN];
    const int tid = threadIdx.x;
    const size_t m0 = (size_t)blockIdx.y * BM;
    const int n0 = blockIdx.x * BN;
    const int tr = tid >> 4, tc = tid & 15;
    const int aRow = tid >> 1, aCol = (tid & 1) * 8;
    const int wRow = tid >> 4, wCol = (tid & 15) * 8;

    unsigned long long acc[8][4];
#pragma unroll
    for (int i = 0; i < 8; i++)
#pragma unroll
        for (int jj = 0; jj < 4; jj++) acc[i][jj] = 0ULL;

    const float* Abase = A + (m0 + aRow) * (size_t)NIN + aCol;
    const float* Wbase = W + (size_t)wRow * HPAD + n0 + wCol;
    const uint32_t ws_s0 = smem_u32(&Ws[0][wRow][wCol]);
    const uint32_t ws_s1 = smem_u32(&Ws[1][wRow][wCol]);

    // prologue: W(0) via cp.async, A(0) into regs
    cpasync16(ws_s0, Wbase);
    cpasync16(ws_s0 + 16, Wbase + 4);
    asm volatile("cp.async.commit_group;" ::: "memory");
    float4 av0 = *(const float4*)(Abase);
    float4 av1 = *(const float4*)(Abase + 4);

#pragma unroll 1
    for (int c = 0; c < NCH1; c++) {
        const int buf = c & 1;
        As[buf][aCol + 0][aRow] = av0.x; As[buf][aCol + 1][aRow] = av0.y;
        As[buf][aCol + 2][aRow] = av0.z; As[buf][aCol + 3][aRow] = av0.w;
        As[buf][aCol + 4][aRow] = av1.x; As[buf][aCol + 5][aRow] = av1.y;
        As[buf][aCol + 6][aRow] = av1.z; As[buf][aCol + 7][aRow] = av1.w;
        asm volatile("cp.async.wait_group 0;" ::: "memory");
        __syncthreads();
        if (c < NCH1 - 1) {
            const uint32_t wd = (buf ? ws_s0 : ws_s1);
            const float* wsrc = Wbase + (size_t)(c + 1) * BK * HPAD;
            cpasync16(wd, wsrc);
            cpasync16(wd + 16, wsrc + 4);
            asm volatile("cp.async.commit_group;" ::: "memory");
            av0 = *(const float4*)(Abase + (c + 1) * BK);
            av1 = *(const float4*)(Abase + (c + 1) * BK + 4);
        }
#pragma unroll
        for (int k = 0; k < BK; k++) {
            float ra[8];
            *(float4*)(&ra[0]) = *(const float4*)(&As[buf][k][tr * 8]);
            *(float4*)(&ra[4]) = *(const float4*)(&As[buf][k][tr * 8 + 4]);
            unsigned long long rb[4];
            rb[0] = *(const unsigned long long*)(&Ws[buf][k][tc * 4]);
            rb[1] = *(const unsigned long long*)(&Ws[buf][k][tc * 4 + 2]);
            rb[2] = *(const unsigned long long*)(&Ws[buf][k][64 + tc * 4]);
            rb[3] = *(const unsigned long long*)(&Ws[buf][k][64 + tc * 4 + 2]);
#pragma unroll
            for (int i = 0; i < 8; i++) {
                unsigned long long aa = dup2(ra[i]);
                ffma2(acc[i][0], aa, rb[0]);
                ffma2(acc[i][1], aa, rb[1]);
                ffma2(acc[i][2], aa, rb[2]);
                ffma2(acc[i][3], aa, rb[3]);
            }
        }
    }

    const int nA = n0 + tc * 4, nB = n0 + 64 + tc * 4;
    float4 bvA = *(const float4*)(bias + nA);
    float4 bvB = *(const float4*)(bias + nB);
#pragma unroll
    for (int i = 0; i < 8; i++) {
        size_t rowOff = (m0 + tr * 8 + i) * (size_t)HPAD;
        float2 p0 = unpack2(acc[i][0]), p1 = unpack2(acc[i][1]);
        float2 p2 = unpack2(acc[i][2]), p3 = unpack2(acc[i][3]);
        float4 cA = {p0.x + bvA.x, p0.y + bvA.y, p1.x + bvA.z, p1.y + bvA.w};
        float4 cB = {p2.x + bvB.x, p2.y + bvB.y, p3.x + bvB.z, p3.y + bvB.w};
        *(float4*)(C + rowOff + nA) = cA;
        *(float4*)(C + rowOff + nB) = cB;
    }
}

// ================= layer-2 GEMM via mma.sync fp16 (2-split, K=512) =================
// A operand: s1 spike bitmask expanded to fp16 in smem (bit j of word m*8+katom*2+half
// <-> col half*32+j). grid (2, 4000): x = N-tile, y = M-tile.
#define OFF_A0 0
#define OFF_A1 16384
#define OFF_B0 32768
#define OFF_B1 49152
#define G2_SMEM 65536
#define NCHUNK 8

__global__ __launch_bounds__(256, 2)
void gemm2_mma_kernel(const uint32_t* __restrict__ s1bits,
                      const __half* __restrict__ W2h,
                      float* __restrict__ out) {
    extern __shared__ __align__(1024) char smem[];
    const uint32_t sb = smem_u32(smem);
    const int tid = threadIdx.x;
    const int warp = tid >> 5, lane = tid & 31;
    const int g = lane >> 2, tig = lane & 3;
    const int wm = warp >> 2, wn = warp & 3;
    const size_t m0 = (size_t)blockIdx.y * 128;
    const int n0 = blockIdx.x * 128;

    const int ldr = tid >> 1;       // row 0..127
    const int ldh = tid & 1;        // half-row
    const uint32_t ldst = swz((uint32_t)(ldr * 128 + ldh * 64));

    const int arow_l = lane & 15, ahalf = lane >> 4;
    const uint32_t a_off0 = (uint32_t)((wm * 64 + arow_l) * 128 + ahalf * 16);
    const int lane8 = lane & 7, laneg = lane >> 3;
    const uint32_t b_off0 =
        (uint32_t)((wn * 32 + ((laneg & 2) ? 8 : 0) + lane8) * 128 + (laneg & 1) * 16);

    float acc[4][4][4];
#pragma unroll
    for (int mf = 0; mf < 4; mf++)
#pragma unroll
        for (int nf = 0; nf < 4; nf++)
#pragma unroll
            for (int q = 0; q < 4; q++) acc[mf][nf][q] = 0.0f;

    // per-thread bit-word pointer: word = (m0+ldr)*8 + katom*2 + ldh
    const uint32_t* abits = s1bits + (m0 + ldr) * 8 + ldh;
    const __half* bsrc = W2h + (size_t)(n0 + ldr) * KCAT2 + ldh * 32;

    // expand one katom's bits into A smem buffer (identical layout to old cp.async)
    auto expand_a = [&](int katom, int aoff) {
        uint32_t w = __ldg(abits + katom * 2);
        char* dst = smem + aoff;
#pragma unroll
        for (int j = 0; j < 4; j++) {
            uint32_t pk[4];
#pragma unroll
            for (int p = 0; p < 4; p++) {
                uint32_t two = (w >> (8 * j + 2 * p)) & 3u;
                pk[p] = ((two & 1u) ? 0x3C00u : 0u) | ((two & 2u) ? 0x3C000000u : 0u);
            }
            *(uint4*)(dst + (ldst ^ (j * 16))) = *(uint4*)pk;
        }
    };

    // prologue: A(katom 0) expand into A0, B chunk 0 via cp.async
    expand_a(0, OFF_A0);
#pragma unroll
    for (int j = 0; j < 4; j++) cpasync16(sb + OFF_B0 + (ldst ^ (j * 16)), bsrc + j * 8);
    asm volatile("cp.async.commit_group;" ::: "memory");

#pragma unroll 1
    for (int c = 0; c < NCHUNK; c++) {
        if (c < NCHUNK - 1) {
            const int cn = c + 1;
            if ((cn & 1) == 0)  // new katom -> expand bits into the other A buffer
                expand_a(cn >> 1, ((cn >> 1) & 1) ? OFF_A1 : OFF_A0);
            const uint32_t bb = sb + ((cn & 1) ? OFF_B1 : OFF_B0);
            const __half* src = bsrc + cn * 64;
#pragma unroll
            for (int j = 0; j < 4; j++) cpasync16(bb + (ldst ^ (j * 16)), src + j * 8);
            asm volatile("cp.async.commit_group;" ::: "memory");
            asm volatile("cp.async.wait_group 1;" ::: "memory");
        } else {
            asm volatile("cp.async.wait_group 0;" ::: "memory");
        }
        __syncthreads();

        const uint32_t ab = sb + (((c >> 1) & 1) ? OFF_A1 : OFF_A0);
        const uint32_t bb = sb + ((c & 1) ? OFF_B1 : OFF_B0);
#pragma unroll
        for (int ks = 0; ks < 4; ks++) {
            uint32_t afr[4][4];
#pragma unroll
            for (int mf = 0; mf < 4; mf++)
                ldsm4(afr[mf], ab + swz(a_off0 + (uint32_t)(mf * 16 * 128 + ks * 32)));
            uint32_t bfr[4][2];
            ldsm4(&bfr[0][0], bb + swz(b_off0 + (uint32_t)(ks * 32)));
            ldsm4(&bfr[2][0], bb + swz(b_off0 + (uint32_t)(16 * 128 + ks * 32)));
#pragma unroll
            for (int mf = 0; mf < 4; mf++)
#pragma unroll
                for (int nf = 0; nf < 4; nf++)
                    mma_f16(acc[mf][nf], afr[mf], bfr[nf]);
        }
        __syncthreads();
    }

#pragma unroll
    for (int mf = 0; mf < 4; mf++) {
        size_t r0 = (m0 + wm * 64 + mf * 16 + g) * HPAD;
#pragma unroll
        for (int nf = 0; nf < 4; nf++) {
            int col = n0 + wn * 32 + nf * 8 + tig * 2;
            *(float2*)(out + r0 + col) = make_float2(acc[mf][nf][0], acc[mf][nf][1]);
            *(float2*)(out + r0 + 8 * HPAD + col) = make_float2(acc[mf][nf][2], acc[mf][nf][3]);
        }
    }
}

// ================= LIF scans (1 lane per thread, bitmask spikes) =================
__global__ void lif_scan1_kernel(const float* __restrict__ buf,
                                 uint32_t* __restrict__ s1bits) {
    int id = blockIdx.x * blockDim.x + threadIdx.x;  // 0..131071 = b*256+h
    int lane = id & 31;
    int word = id >> 5;
    float m = 0.0f;
    size_t idx = id;
#pragma unroll 8
    for (int t = 0; t < T_STEPS; t++) {
        float cur = buf[idx];
        float r = (m > 1.0f) ? 1.0f : 0.0f;
        m = __fadd_rn(__fadd_rn(__fmul_rn(0.9f, m), cur), -r);
        uint32_t bal = __ballot_sync(0xffffffffu, m > 1.0f);
        if (lane == 0) s1bits[(size_t)t * (LANES / 32) + word] = bal;
        idx += LANES;
    }
}
__global__ void lif_scan2_kernel(const float* __restrict__ buf,
                                 const float* __restrict__ bias,
                                 uint32_t* __restrict__ s2bits) {
    int id = blockIdx.x * blockDim.x + threadIdx.x;
    int lane = id & 31;
    int word = id >> 5;
    float bv = bias[id & 255];
    float m = 0.0f;
    size_t idx = id;
#pragma unroll 8
    for (int t = 0; t < T_STEPS; t++) {
        float cur = __fadd_rn(buf[idx], bv);
        float r = (m > 1.0f) ? 1.0f : 0.0f;
        m = __fadd_rn(__fadd_rn(__fmul_rn(0.9f, m), cur), -r);
        uint32_t bal = __ballot_sync(0xffffffffu, m > 1.0f);
        if (lane == 0) s2bits[(size_t)t * (LANES / 32) + word] = bal;
        idx += LANES;
    }
}

// ---- layer 3 GEMM over spike bitmask: warp-per-row, N=2, K=256 ----
__global__ __launch_bounds__(256)
void gemm3_kernel(const uint32_t* __restrict__ s2bits, const float* __restrict__ W3,
                  const float* __restrict__ b3, float* __restrict__ cur3) {
    __shared__ float w0[HPAD], w1[HPAD];
    int tid = threadIdx.x;
    if (tid < 250) { w0[tid] = W3[tid * 2]; w1[tid] = W3[tid * 2 + 1]; }
    else           { w0[tid] = 0.0f;        w1[tid] = 0.0f; }
    __syncthreads();
    int warp = tid >> 5, lane = tid & 31;
    size_t row = (size_t)blockIdx.x * 8 + warp;
    uint32_t wbits = __ldg(s2bits + row * 8 + (lane >> 2));
    uint32_t byte = (wbits >> ((lane & 3) * 8)) & 0xFFu;
    float a0 = 0.0f, a1 = 0.0f;
    int k0 = lane * 8;
#pragma unroll
    for (int j = 0; j < 8; j++) {
        if (byte & (1u << j)) {
            a0 += w0[k0 + j];
            a1 += w1[k0 + j];
        }
    }
#pragma unroll
    for (int off = 16; off; off >>= 1) {
        a0 += __shfl_xor_sync(0xffffffffu, a0, off);
        a1 += __shfl_xor_sync(0xffffffffu, a1, off);
    }
    if (lane == 0) {
        cur3[row * 2 + 0] = a0 + b3[0];
        cur3[row * 2 + 1] = a1 + b3[1];
    }
}

__global__ void lif3_kernel(const float* __restrict__ cur3, float* __restrict__ out) {
    int lane = blockIdx.x * blockDim.x + threadIdx.x;
    float m = 0.0f;
#pragma unroll 16
    for (int t = 0; t < T_STEPS; t++) {
        float cur = cur3[t * 1024 + lane];
        float r = (m > 1.0f) ? 1.0f : 0.0f;
        m = __fadd_rn(__fadd_rn(__fmul_rn(0.9f, m), cur), -r);
        out[t * 1024 + lane] = (m > 1.0f) ? 1.0f : 0.0f;
        out[OUTB + t * 1024 + lane] = m;
    }
}

extern "C" void kernel_launch(void* const* d_in, const int* in_sizes, int n_in,
                              void* d_out, int out_size) {
    const float* x  = (const float*)d_in[0];
    const float* W1 = (const float*)d_in[1];
    const float* b1 = (const float*)d_in[2];
    const float* W2 = (const float*)d_in[3];
    const float* b2 = (const float*)d_in[4];
    const float* W3 = (const float*)d_in[5];
    const float* b3 = (const float*)d_in[6];
    float* out = (float*)d_out;

    float *buf1, *buf2, *cur3, *W1p, *b1p, *b2p;
    __half *W2h;
    uint32_t *s1bits, *s2bits;
    cudaGetSymbolAddress((void**)&buf1, g_buf1);
    cudaGetSymbolAddress((void**)&buf2, g_buf2);
    cudaGetSymbolAddress((void**)&cur3, g_cur3);
    cudaGetSymbolAddress((void**)&W1p, g_W1p);
    cudaGetSymbolAddress((void**)&b1p, g_b1p);
    cudaGetSymbolAddress((void**)&b2p, g_b2p);
    cudaGetSymbolAddress((void**)&s1bits, g_s1bits);
    cudaGetSymbolAddress((void**)&s2bits, g_s2bits);
    cudaGetSymbolAddress((void**)&W2h, g_W2h);

    cudaFuncSetAttribute(gemm2_mma_kernel,
                         cudaFuncAttributeMaxDynamicSharedMemorySize, G2_SMEM);

    prep_kernel<<<128, 256>>>(W1, b1, b2);
    prep_w2h_kernel<<<512, 256>>>(W2);

    // layer 1: cur1 = x @ W1 + b1 (exact FFMA2 fp32, pipelined)
    sgemm_kernel<<<dim3(HPAD / BN, MROWS / BM), 256>>>(x, W1p, b1p, buf1);
    lif_scan1_kernel<<<LANES / 256, 256>>>(buf1, s1bits);

    // layer 2: cur2 = s1 @ (W2hi + W2lo), A expanded from bitmask in smem
    gemm2_mma_kernel<<<dim3(2, MROWS / 128), 256, G2_SMEM>>>(s1bits, W2h, buf2);
    lif_scan2_kernel<<<LANES / 256, 256>>>(buf2, b2p, s2bits);

    // layer 3 over spike bitmask
    gemm3_kernel<<<MROWS / 8, 256>>>(s2bits, W3, b3, cur3);
    lif3_kernel<<<4, 256>>>(cur3, out);
}